// round 8
// baseline (speedup 1.0000x reference)
#include <cuda_runtime.h>

#define HID    64
#define ENC_T  20
#define DEC_T  30
#define TB     64          // batch elements per CTA
#define NTH    256         // threads per CTA
#define GATES  256         // 4*HID, reordered col = u*4 + gate
#define HS     66          // h_s row stride in floats (bank-safe)

typedef unsigned long long u64;

// ---- packed fp32x2 helpers (Blackwell FFMA2 — only reachable via PTX) ----
__device__ __forceinline__ u64 fma2(u64 a, u64 b, u64 c) {
    u64 d;
    asm("fma.rn.f32x2 %0, %1, %2, %3;" : "=l"(d) : "l"(a), "l"(b), "l"(c));
    return d;
}
__device__ __forceinline__ u64 pack2(float x) {
    u64 d; unsigned xi = __float_as_uint(x);
    asm("mov.b64 %0, {%1, %1};" : "=l"(d) : "r"(xi));
    return d;
}
__device__ __forceinline__ void unpk(u64 v, float& a, float& b) {
    unsigned ai, bi;
    asm("mov.b64 {%0, %1}, %2;" : "=r"(ai), "=r"(bi) : "l"(v));
    a = __uint_as_float(ai); b = __uint_as_float(bi);
}

// ---- activations: MUFU-based, fp32-accurate enough (~1e-6 rel), overflow-safe ----
__device__ __forceinline__ float sigm(float x) {
    return __fdividef(1.f, 1.f + __expf(-x));   // x << 0: exp->inf, 1/inf -> 0  (ok)
}
__device__ __forceinline__ float tanh_f(float x) {
    x = fminf(fmaxf(x, -15.f), 15.f);           // clamp so exp(-2x) stays finite
    float e = __expf(-2.f * x);
    return __fdividef(1.f - e, 1.f + e);
}

__global__ void __launch_bounds__(NTH, 2)
lstm_seq2seq(const float* __restrict__ traj,
             const float* __restrict__ Wih_e, const float* __restrict__ Whh_e,
             const float* __restrict__ bih_e, const float* __restrict__ bhh_e,
             const float* __restrict__ Wih_d, const float* __restrict__ Whh_d,
             const float* __restrict__ bih_d, const float* __restrict__ bhh_d,
             const float* __restrict__ Wpos,  const float* __restrict__ bpos,
             float* __restrict__ out, int B)
{
    extern __shared__ float sm[];
    float* w_s    = sm;                          // [64][256]  k-major, col = u*4+g
    float* h_s    = w_s + HID * GATES;           // [64][HS]   h[u][b]
    float* x_s    = h_s + HID * HS;              // [TB][2*ENC_T]
    float* bias_s = x_s + TB * 2 * ENC_T;        // [256]
    float* xw0_s  = bias_s + GATES;              // [256]  W_ih_enc[:,0] reordered
    float* xw1_s  = xw0_s + GATES;               // [256]  W_ih_enc[:,1] reordered
    float* wpos_s = xw1_s + GATES;               // [2][64]
    float* bpos_s = wpos_s + 2 * HID;            // [2]

    const int tid   = threadIdx.x;
    const int b     = tid & (TB - 1);            // batch lane (coalesced in SMEM)
    const int gbase = (tid >> 6) << 6;           // 0,64,128,192 (warp-uniform)
    const int ubase = gbase >> 2;                // 0,16,32,48
    const int b0    = blockIdx.x * TB;
    const bool bvalid = (b0 + b) < B;

    // ---------------- setup ----------------
    // encoder recurrent weights, reordered: w_s[k][u*4+g] = W_hh_enc[g*64+u][k]
    for (int i = tid; i < HID * GATES; i += NTH) {
        int row = i >> 6, k = i & 63;
        int col = ((row & 63) << 2) | (row >> 6);
        w_s[k * GATES + col] = Whh_e[i];
    }
    for (int i = tid; i < GATES; i += NTH) {
        int col = ((i & 63) << 2) | (i >> 6);
        bias_s[col] = bih_e[i] + bhh_e[i];
        xw0_s[col]  = Wih_e[2 * i];
        xw1_s[col]  = Wih_e[2 * i + 1];
    }
    for (int i = tid; i < TB * 2 * ENC_T; i += NTH) {
        int bb = i / (2 * ENC_T);
        x_s[i] = (b0 + bb < B) ? traj[(size_t)b0 * 2 * ENC_T + i] : 0.f;
    }
    for (int i = tid; i < HID * HS; i += NTH) h_s[i] = 0.f;
    if (tid < 2 * HID) wpos_s[tid] = Wpos[tid];
    if (tid < 2)       bpos_s[tid] = bpos[tid];

    float c[16], hreg[16];
    #pragma unroll
    for (int j = 0; j < 16; j++) c[j] = 0.f;

    __syncthreads();

    // ---------------- encoder: 20 steps ----------------
    for (int t = 0; t < ENC_T; t++) {
        u64 acc[32];
        // init: bias + x_t @ W_ih_enc^T  (K extension of just 2)
        {
            float x0 = x_s[b * 2 * ENC_T + 2 * t];
            float x1 = x_s[b * 2 * ENC_T + 2 * t + 1];
            u64 x02 = pack2(x0), x12 = pack2(x1);
            const ulonglong2* bp = (const ulonglong2*)(bias_s + gbase);
            const ulonglong2* p0 = (const ulonglong2*)(xw0_s + gbase);
            const ulonglong2* p1 = (const ulonglong2*)(xw1_s + gbase);
            #pragma unroll
            for (int m = 0; m < 16; m++) {
                ulonglong2 bb = bp[m], w0 = p0[m], w1 = p1[m];
                acc[2*m]   = fma2(x12, w1.x, fma2(x02, w0.x, bb.x));
                acc[2*m+1] = fma2(x12, w1.y, fma2(x02, w0.y, bb.y));
            }
        }
        // gates += h @ W_hh^T  : weight loads broadcast, h load coalesced
        #pragma unroll 2
        for (int k = 0; k < HID; k++) {
            u64 hk = pack2(h_s[k * HS + b]);
            const ulonglong2* wr = (const ulonglong2*)(w_s + k * GATES + gbase);
            #pragma unroll
            for (int m = 0; m < 16; m++) {
                ulonglong2 ww = wr[m];
                acc[2*m]   = fma2(hk, ww.x, acc[2*m]);
                acc[2*m+1] = fma2(hk, ww.y, acc[2*m+1]);
            }
        }
        // activations (registers only) — acc[2u]=(i,f), acc[2u+1]=(g,o)
        #pragma unroll
        for (int uu = 0; uu < 16; uu++) {
            float gi, gf, gg, go;
            unpk(acc[2*uu],   gi, gf);
            unpk(acc[2*uu+1], gg, go);
            float cn = sigm(gf) * c[uu] + sigm(gi) * tanh_f(gg);
            c[uu]    = cn;
            hreg[uu] = sigm(go) * tanh_f(cn);
        }
        __syncthreads();                         // all reads of old h done
        #pragma unroll
        for (int uu = 0; uu < 16; uu++)
            h_s[(ubase + uu) * HS + b] = hreg[uu];
        __syncthreads();                         // new h visible
    }

    // ---------------- swap weights: decoder (W_ih + W_hh fused, input == h) ----------------
    for (int i = tid; i < HID * GATES; i += NTH) {
        int row = i >> 6, k = i & 63;
        int col = ((row & 63) << 2) | (row >> 6);
        w_s[k * GATES + col] = Wih_d[i] + Whh_d[i];
    }
    for (int i = tid; i < GATES; i += NTH) {
        int col = ((i & 63) << 2) | (i >> 6);
        bias_s[col] = bih_d[i] + bhh_d[i];
    }
    __syncthreads();

    // ---------------- decoder: 30 steps ----------------
    for (int t = 0; t < DEC_T; t++) {
        u64 acc[32];
        {
            const ulonglong2* bp = (const ulonglong2*)(bias_s + gbase);
            #pragma unroll
            for (int m = 0; m < 16; m++) {
                ulonglong2 bb = bp[m];
                acc[2*m] = bb.x; acc[2*m+1] = bb.y;
            }
        }
        #pragma unroll 2
        for (int k = 0; k < HID; k++) {
            u64 hk = pack2(h_s[k * HS + b]);
            const ulonglong2* wr = (const ulonglong2*)(w_s + k * GATES + gbase);
            #pragma unroll
            for (int m = 0; m < 16; m++) {
                ulonglong2 ww = wr[m];
                acc[2*m]   = fma2(hk, ww.x, acc[2*m]);
                acc[2*m+1] = fma2(hk, ww.y, acc[2*m+1]);
            }
        }
        // emit output for previous step (h_s currently holds h after dec step t-1)
        if (t >= 1 && tid < 2 * TB && bvalid) {
            int j = tid >> 6;                    // 0 or 1
            float a = bpos_s[j];
            #pragma unroll
            for (int u = 0; u < HID; u++)
                a += h_s[u * HS + b] * wpos_s[j * HID + u];
            out[(size_t)(b0 + b) * (2 * DEC_T) + 2 * (t - 1) + j] = a;
        }
        #pragma unroll
        for (int uu = 0; uu < 16; uu++) {
            float gi, gf, gg, go;
            unpk(acc[2*uu],   gi, gf);
            unpk(acc[2*uu+1], gg, go);
            float cn = sigm(gf) * c[uu] + sigm(gi) * tanh_f(gg);
            c[uu]    = cn;
            hreg[uu] = sigm(go) * tanh_f(cn);
        }
        __syncthreads();
        #pragma unroll
        for (int uu = 0; uu < 16; uu++)
            h_s[(ubase + uu) * HS + b] = hreg[uu];
        __syncthreads();
    }

    // final step's output
    if (tid < 2 * TB && bvalid) {
        int j = tid >> 6;
        float a = bpos_s[j];
        #pragma unroll
        for (int u = 0; u < HID; u++)
            a += h_s[u * HS + b] * wpos_s[j * HID + u];
        out[(size_t)(b0 + b) * (2 * DEC_T) + 2 * (DEC_T - 1) + j] = a;
    }
}

extern "C" void kernel_launch(void* const* d_in, const int* in_sizes, int n_in,
                              void* d_out, int out_size) {
    const float* traj  = (const float*)d_in[0];
    const float* Wih_e = (const float*)d_in[1];
    const float* Whh_e = (const float*)d_in[2];
    const float* bih_e = (const float*)d_in[3];
    const float* bhh_e = (const float*)d_in[4];
    const float* Wih_d = (const float*)d_in[5];
    const float* Whh_d = (const float*)d_in[6];
    const float* bih_d = (const float*)d_in[7];
    const float* bhh_d = (const float*)d_in[8];
    const float* Wpos  = (const float*)d_in[9];
    const float* bpos  = (const float*)d_in[10];
    float* out = (float*)d_out;

    int B = in_sizes[0] / (2 * ENC_T);
    int grid = (B + TB - 1) / TB;

    size_t smem_floats = (size_t)HID * GATES   // w_s
                       + (size_t)HID * HS      // h_s
                       + (size_t)TB * 2 * ENC_T// x_s
                       + GATES * 3             // bias, xw0, xw1
                       + 2 * HID + 2 + 8;      // wpos, bpos, slack
    size_t smem = smem_floats * sizeof(float); // ~96.3 KB -> occupancy 2

    cudaFuncSetAttribute(lstm_seq2seq,
                         cudaFuncAttributeMaxDynamicSharedMemorySize, (int)smem);

    lstm_seq2seq<<<grid, NTH, smem>>>(traj, Wih_e, Whh_e, bih_e, bhh_e,
                                      Wih_d, Whh_d, bih_d, bhh_d,
                                      Wpos, bpos, out, B);
}

// round 9
// speedup vs baseline: 1.0388x; 1.0388x over previous
#include <cuda_runtime.h>

#define HID    64
#define ENC_T  20
#define DEC_T  30
#define TB     128         // batch elements per CTA
#define NTH    512         // threads per CTA (16 warps)
#define GATES  256         // 4*HID, reordered col = u*4 + gate
#define XROW   41          // x_s row stride (odd -> conflict-free strided access)

typedef unsigned long long u64;

// ---- packed fp32x2 helpers (Blackwell FFMA2 — only reachable via PTX) ----
__device__ __forceinline__ u64 fma2(u64 a, u64 b, u64 c) {
    u64 d;
    asm("fma.rn.f32x2 %0, %1, %2, %3;" : "=l"(d) : "l"(a), "l"(b), "l"(c));
    return d;
}
__device__ __forceinline__ u64 pack2(float x) {
    u64 d; unsigned xi = __float_as_uint(x);
    asm("mov.b64 %0, {%1, %1};" : "=l"(d) : "r"(xi));
    return d;
}
__device__ __forceinline__ void unpk(u64 v, float& a, float& b) {
    unsigned ai, bi;
    asm("mov.b64 {%0, %1}, %2;" : "=r"(ai), "=r"(bi) : "l"(v));
    a = __uint_as_float(ai); b = __uint_as_float(bi);
}

// ---- activations: MUFU-based, fp32-accurate (~1e-6 rel), overflow-safe ----
__device__ __forceinline__ float sigm(float x) {
    return __fdividef(1.f, 1.f + __expf(-x));
}
__device__ __forceinline__ float tanh_f(float x) {
    x = fminf(fmaxf(x, -15.f), 15.f);
    float e = __expf(-2.f * x);
    return __fdividef(1.f - e, 1.f + e);
}

__global__ void __launch_bounds__(NTH, 1)
lstm_seq2seq(const float* __restrict__ traj,
             const float* __restrict__ Wih_e, const float* __restrict__ Whh_e,
             const float* __restrict__ bih_e, const float* __restrict__ bhh_e,
             const float* __restrict__ Wih_d, const float* __restrict__ Whh_d,
             const float* __restrict__ bih_d, const float* __restrict__ bhh_d,
             const float* __restrict__ Wpos,  const float* __restrict__ bpos,
             float* __restrict__ out, int B)
{
    extern __shared__ float sm[];
    float* w_s    = sm;                            // [64][256] k-major, col=u*4+g
    u64*   h2     = (u64*)(sm + HID * GATES);      // [64][128] (h,h) duplicated pairs
    float* x_s    = sm + HID * GATES + HID * TB * 2; // [128][XROW]
    float* bias_s = x_s + TB * XROW;               // [256]
    float* xw0_s  = bias_s + GATES;                // [256]
    float* xw1_s  = xw0_s + GATES;                 // [256]
    float* wpos_s = xw1_s + GATES;                 // [2][64]
    float* bpos_s = wpos_s + 2 * HID;              // [2]

    const int tid   = threadIdx.x;
    const int lane  = tid & 31;
    const int warp  = tid >> 5;                    // 0..15, owns 16 gate cols
    const int jbase = warp << 4;                   // gate-col base (multiple of 16)
    const int ubase = warp << 2;                   // 4 local hidden units
    const int b0    = blockIdx.x * TB;

    // ---------------- setup ----------------
    // encoder recurrent weights, reordered: w_s[k][u*4+g] = W_hh_enc[g*64+u][k]
    for (int i = tid; i < HID * GATES; i += NTH) {
        int row = i >> 6, k = i & 63;
        int col = ((row & 63) << 2) | (row >> 6);
        w_s[k * GATES + col] = Whh_e[i];
    }
    for (int i = tid; i < GATES; i += NTH) {
        int col = ((i & 63) << 2) | (i >> 6);
        bias_s[col] = bih_e[i] + bhh_e[i];
        xw0_s[col]  = Wih_e[2 * i];
        xw1_s[col]  = Wih_e[2 * i + 1];
    }
    for (int i = tid; i < TB * 2 * ENC_T; i += NTH) {
        int bb = i / (2 * ENC_T), r = i % (2 * ENC_T);
        x_s[bb * XROW + r] = (b0 + bb < B) ? traj[(size_t)b0 * 2 * ENC_T + i] : 0.f;
    }
    for (int i = tid; i < HID * TB; i += NTH) h2[i] = 0ull;   // h = 0
    if (tid < 2 * HID) wpos_s[tid] = Wpos[tid];
    if (tid < 2)       bpos_s[tid] = bpos[tid];

    float c[4][4];                                 // [batch s][local unit]
    #pragma unroll
    for (int s = 0; s < 4; s++)
        #pragma unroll
        for (int u = 0; u < 4; u++) c[s][u] = 0.f;

    __syncthreads();

    // ---------------- encoder: 20 steps ----------------
    for (int t = 0; t < ENC_T; t++) {
        u64 acc[4][8];                             // [batch s][gate pair]
        {   // init: bias + x_t @ W_ih_enc^T
            const ulonglong2* bp = (const ulonglong2*)(bias_s + jbase);
            const ulonglong2* p0 = (const ulonglong2*)(xw0_s + jbase);
            const ulonglong2* p1 = (const ulonglong2*)(xw1_s + jbase);
            ulonglong2 bb[4], w0[4], w1[4];
            #pragma unroll
            for (int m = 0; m < 4; m++) { bb[m]=bp[m]; w0[m]=p0[m]; w1[m]=p1[m]; }
            #pragma unroll
            for (int s = 0; s < 4; s++) {
                int bl = lane + 32 * s;
                u64 x02 = pack2(x_s[bl * XROW + 2 * t]);
                u64 x12 = pack2(x_s[bl * XROW + 2 * t + 1]);
                #pragma unroll
                for (int m = 0; m < 4; m++) {
                    acc[s][2*m]   = fma2(x12, w1[m].x, fma2(x02, w0[m].x, bb[m].x));
                    acc[s][2*m+1] = fma2(x12, w1[m].y, fma2(x02, w0[m].y, bb[m].y));
                }
            }
        }
        // gates += h @ W_hh^T
        #pragma unroll 4
        for (int k = 0; k < HID; k++) {
            const u64* hr = h2 + k * TB;
            u64 h0 = hr[lane], h1 = hr[lane+32], hv2 = hr[lane+64], h3 = hr[lane+96];
            const ulonglong2* wr = (const ulonglong2*)(w_s + k * GATES + jbase);
            ulonglong2 w0 = wr[0], w1 = wr[1], w2 = wr[2], w3 = wr[3];
            #pragma unroll
            for (int m = 0; m < 4; m++) {
                ulonglong2 ww = (m==0)?w0:(m==1)?w1:(m==2)?w2:w3;
                acc[0][2*m]   = fma2(h0,  ww.x, acc[0][2*m]);
                acc[0][2*m+1] = fma2(h0,  ww.y, acc[0][2*m+1]);
                acc[1][2*m]   = fma2(h1,  ww.x, acc[1][2*m]);
                acc[1][2*m+1] = fma2(h1,  ww.y, acc[1][2*m+1]);
                acc[2][2*m]   = fma2(hv2, ww.x, acc[2][2*m]);
                acc[2][2*m+1] = fma2(hv2, ww.y, acc[2][2*m+1]);
                acc[3][2*m]   = fma2(h3,  ww.x, acc[3][2*m]);
                acc[3][2*m+1] = fma2(h3,  ww.y, acc[3][2*m+1]);
            }
        }
        // activations: acc[s][2u]=(i,f), acc[s][2u+1]=(g,o)
        u64 hnew[4][4];
        #pragma unroll
        for (int s = 0; s < 4; s++)
            #pragma unroll
            for (int uu = 0; uu < 4; uu++) {
                float gi, gf, gg, go;
                unpk(acc[s][2*uu],   gi, gf);
                unpk(acc[s][2*uu+1], gg, go);
                float cn = sigm(gf) * c[s][uu] + sigm(gi) * tanh_f(gg);
                c[s][uu] = cn;
                hnew[s][uu] = pack2(sigm(go) * tanh_f(cn));
            }
        __syncthreads();                           // all reads of old h done
        #pragma unroll
        for (int uu = 0; uu < 4; uu++)
            #pragma unroll
            for (int s = 0; s < 4; s++)
                h2[(ubase + uu) * TB + lane + 32 * s] = hnew[s][uu];
        __syncthreads();                           // new h visible
    }

    // ---------------- swap weights: decoder (input == h -> fuse W_ih+W_hh) ----------------
    for (int i = tid; i < HID * GATES; i += NTH) {
        int row = i >> 6, k = i & 63;
        int col = ((row & 63) << 2) | (row >> 6);
        w_s[k * GATES + col] = Wih_d[i] + Whh_d[i];
    }
    for (int i = tid; i < GATES; i += NTH) {
        int col = ((i & 63) << 2) | (i >> 6);
        bias_s[col] = bih_d[i] + bhh_d[i];
    }
    __syncthreads();

    // ---------------- decoder: 30 steps ----------------
    for (int t = 0; t < DEC_T; t++) {
        u64 acc[4][8];
        {
            const ulonglong2* bp = (const ulonglong2*)(bias_s + jbase);
            #pragma unroll
            for (int m = 0; m < 4; m++) {
                ulonglong2 bb = bp[m];
                #pragma unroll
                for (int s = 0; s < 4; s++) { acc[s][2*m] = bb.x; acc[s][2*m+1] = bb.y; }
            }
        }
        #pragma unroll 4
        for (int k = 0; k < HID; k++) {
            const u64* hr = h2 + k * TB;
            u64 h0 = hr[lane], h1 = hr[lane+32], hv2 = hr[lane+64], h3 = hr[lane+96];
            const ulonglong2* wr = (const ulonglong2*)(w_s + k * GATES + jbase);
            ulonglong2 w0 = wr[0], w1 = wr[1], w2 = wr[2], w3 = wr[3];
            #pragma unroll
            for (int m = 0; m < 4; m++) {
                ulonglong2 ww = (m==0)?w0:(m==1)?w1:(m==2)?w2:w3;
                acc[0][2*m]   = fma2(h0,  ww.x, acc[0][2*m]);
                acc[0][2*m+1] = fma2(h0,  ww.y, acc[0][2*m+1]);
                acc[1][2*m]   = fma2(h1,  ww.x, acc[1][2*m]);
                acc[1][2*m+1] = fma2(h1,  ww.y, acc[1][2*m+1]);
                acc[2][2*m]   = fma2(hv2, ww.x, acc[2][2*m]);
                acc[2][2*m+1] = fma2(hv2, ww.y, acc[2][2*m+1]);
                acc[3][2*m]   = fma2(h3,  ww.x, acc[3][2*m]);
                acc[3][2*m+1] = fma2(h3,  ww.y, acc[3][2*m+1]);
            }
        }
        // emit out for step t-1 (h2 holds h_{t-1}; stable until the write sync)
        if (t >= 1 && tid < 2 * TB) {
            int j = tid >> 7, bl = tid & (TB - 1);
            if (b0 + bl < B) {
                float a = bpos_s[j];
                const float* hp = (const float*)h2;    // (h,h) pairs: stride-2 floats
                #pragma unroll 8
                for (int u = 0; u < HID; u++)
                    a += hp[(u * TB + bl) * 2] * wpos_s[j * HID + u];
                out[(size_t)(b0 + bl) * (2 * DEC_T) + 2 * (t - 1) + j] = a;
            }
        }
        u64 hnew[4][4];
        #pragma unroll
        for (int s = 0; s < 4; s++)
            #pragma unroll
            for (int uu = 0; uu < 4; uu++) {
                float gi, gf, gg, go;
                unpk(acc[s][2*uu],   gi, gf);
                unpk(acc[s][2*uu+1], gg, go);
                float cn = sigm(gf) * c[s][uu] + sigm(gi) * tanh_f(gg);
                c[s][uu] = cn;
                hnew[s][uu] = pack2(sigm(go) * tanh_f(cn));
            }
        __syncthreads();
        #pragma unroll
        for (int uu = 0; uu < 4; uu++)
            #pragma unroll
            for (int s = 0; s < 4; s++)
                h2[(ubase + uu) * TB + lane + 32 * s] = hnew[s][uu];
        __syncthreads();
    }

    // final step's output
    if (tid < 2 * TB) {
        int j = tid >> 7, bl = tid & (TB - 1);
        if (b0 + bl < B) {
            float a = bpos_s[j];
            const float* hp = (const float*)h2;
            #pragma unroll 8
            for (int u = 0; u < HID; u++)
                a += hp[(u * TB + bl) * 2] * wpos_s[j * HID + u];
            out[(size_t)(b0 + bl) * (2 * DEC_T) + 2 * (DEC_T - 1) + j] = a;
        }
    }
}

extern "C" void kernel_launch(void* const* d_in, const int* in_sizes, int n_in,
                              void* d_out, int out_size) {
    const float* traj  = (const float*)d_in[0];
    const float* Wih_e = (const float*)d_in[1];
    const float* Whh_e = (const float*)d_in[2];
    const float* bih_e = (const float*)d_in[3];
    const float* bhh_e = (const float*)d_in[4];
    const float* Wih_d = (const float*)d_in[5];
    const float* Whh_d = (const float*)d_in[6];
    const float* bih_d = (const float*)d_in[7];
    const float* bhh_d = (const float*)d_in[8];
    const float* Wpos  = (const float*)d_in[9];
    const float* bpos  = (const float*)d_in[10];
    float* out = (float*)d_out;

    int B = in_sizes[0] / (2 * ENC_T);
    int grid = (B + TB - 1) / TB;

    size_t smem_floats = (size_t)HID * GATES       // w_s       16384
                       + (size_t)HID * TB * 2      // h2 dup    16384
                       + (size_t)TB * XROW         // x_s        5248
                       + GATES * 3                 // bias/xw0/xw1
                       + 2 * HID + 2 + 14;         // wpos/bpos/slack
    size_t smem = smem_floats * sizeof(float);     // ~152 KB -> 1 CTA/SM

    cudaFuncSetAttribute(lstm_seq2seq,
                         cudaFuncAttributeMaxDynamicSharedMemorySize, (int)smem);

    lstm_seq2seq<<<grid, NTH, smem>>>(traj, Wih_e, Whh_e, bih_e, bhh_e,
                                      Wih_d, Whh_d, bih_d, bhh_d,
                                      Wpos, bpos, out, B);
}

// round 10
// speedup vs baseline: 2.3575x; 2.2693x over previous
#include <cuda_runtime.h>
#include <cuda_bf16.h>

#define HID    64
#define ENC_T  20
#define DEC_T  30
#define TB     128
#define NTH    512
#define NKS    5            // k16 steps: K = 80 (64 h + 2 x + 1 one + 13 zero)
#define AROW   88           // bf16 cols per row of A/h buffer (bank-disjoint stride)
#define TOT_T  (ENC_T + DEC_T)

typedef unsigned int u32;
typedef unsigned long long u64;

// ---- smem byte offsets ----
#define OFF_BHI   0                       // B frags hi: 5120 u64 = 40960 B
#define OFF_BLO   40960                   // B frags lo: 40960 B
#define OFF_HA    81920                   // h/A: 2 bufs x 2 parts x 128 x 88 bf16
#define HA_BUF    45056
#define HA_PART   22528
#define OFF_X     (OFF_HA + 2*HA_BUF)     // x: 128 x 40 f32 = 20480 B
#define OFF_WPOS  (OFF_X + 128*40*4)      // 128 f32
#define OFF_BPOS  (OFF_WPOS + 128*4)      // 2 f32
#define SMEM_SZ   (OFF_BPOS + 16)         // ~193056 B

// ---- activations (proven in R8: rel_err 3.6e-7) ----
__device__ __forceinline__ float sigm(float x) {
    return __fdividef(1.f, 1.f + __expf(-x));
}
__device__ __forceinline__ float tanh_f(float x) {
    x = fminf(fmaxf(x, -15.f), 15.f);
    float e = __expf(-2.f * x);
    return __fdividef(1.f - e, 1.f + e);
}

// ---- mma / ldmatrix wrappers ----
__device__ __forceinline__ void mma16816(float* d, const u32* a, u32 b0, u32 b1) {
    asm("mma.sync.aligned.m16n8k16.row.col.f32.bf16.bf16.f32 "
        "{%0,%1,%2,%3}, {%4,%5,%6,%7}, {%8,%9}, {%0,%1,%2,%3};"
        : "+f"(d[0]), "+f"(d[1]), "+f"(d[2]), "+f"(d[3])
        : "r"(a[0]), "r"(a[1]), "r"(a[2]), "r"(a[3]), "r"(b0), "r"(b1));
}
__device__ __forceinline__ void ldm4(u32* r, u32 addr) {
    asm volatile("ldmatrix.sync.aligned.m8n8.x4.shared.b16 {%0,%1,%2,%3}, [%4];"
        : "=r"(r[0]), "=r"(r[1]), "=r"(r[2]), "=r"(r[3]) : "r"(addr));
}

__device__ __forceinline__ void split_bf16(float v, unsigned short& hb, unsigned short& lb) {
    __nv_bfloat16 hi = __float2bfloat16_rn(v);
    __nv_bfloat16 lo = __float2bfloat16_rn(v - __bfloat162float(hi));
    hb = __bfloat16_as_ushort(hi);
    lb = __bfloat16_as_ushort(lo);
}

// Build B fragments (exact mma layout) into smem. phase 0 = encoder, 1 = decoder.
__device__ __forceinline__ void build_bfrag(char* sm, int tid, int phase,
        const float* __restrict__ W, const float* __restrict__ W2,
        const float* __restrict__ Wx,
        const float* __restrict__ b1v, const float* __restrict__ b2v)
{
    u64* bhi = (u64*)(sm + OFF_BHI);
    u64* blo = (u64*)(sm + OFF_BLO);
    for (int idx = tid; idx < 5120; idx += NTH) {
        int ks = idx >> 10, wn = (idx >> 8) & 3, na = (idx >> 5) & 7, T = idx & 31;
        int cc = T >> 2, tq = T & 3;
        int unit = wn * 16 + ((cc >> 1) << 2) + (na >> 1);
        int gate = ((na & 1) << 1) | (cc & 1);
        int grow = gate * 64 + unit;
        u32 phi[2] = {0, 0}, plo[2] = {0, 0};
        #pragma unroll
        for (int i = 0; i < 2; i++)
            #pragma unroll
            for (int e = 0; e < 2; e++) {
                int k = ks * 16 + tq * 2 + e + 8 * i;
                float v = 0.f;
                if (k < 64)       v = phase ? (W[grow*64+k] + W2[grow*64+k]) : W[grow*64+k];
                else if (k < 66)  v = phase ? 0.f : Wx[grow*2 + (k-64)];
                else if (k == 66) v = b1v[grow] + b2v[grow];
                unsigned short hb, lb;
                split_bf16(v, hb, lb);
                phi[i] |= (u32)hb << (16 * e);
                plo[i] |= (u32)lb << (16 * e);
            }
        bhi[idx] = (u64)phi[0] | ((u64)phi[1] << 32);
        blo[idx] = (u64)plo[0] | ((u64)plo[1] << 32);
    }
}

__device__ __forceinline__ void store_xcol(char* sm, int buf, int row, int sel, float v) {
    unsigned short hb, lb;
    split_bf16(v, hb, lb);
    *(unsigned short*)(sm + OFF_HA + buf*HA_BUF + 0*HA_PART + (row*AROW + 64 + sel)*2) = hb;
    *(unsigned short*)(sm + OFF_HA + buf*HA_BUF + 1*HA_PART + (row*AROW + 64 + sel)*2) = lb;
}

__global__ void __launch_bounds__(NTH, 1)
lstm_mma(const float* __restrict__ traj,
         const float* __restrict__ Wih_e, const float* __restrict__ Whh_e,
         const float* __restrict__ bih_e, const float* __restrict__ bhh_e,
         const float* __restrict__ Wih_d, const float* __restrict__ Whh_d,
         const float* __restrict__ bih_d, const float* __restrict__ bhh_d,
         const float* __restrict__ Wpos,  const float* __restrict__ bpos,
         float* __restrict__ out, int Btot)
{
    extern __shared__ char sm[];
    const int tid  = threadIdx.x;
    const int lane = tid & 31, warp = tid >> 5;
    const int wm   = warp >> 2, wn = warp & 3;      // m-band (rows wm*32), n-band (units wn*16)
    const int quad = lane >> 2, tq = lane & 3;
    const int b0   = blockIdx.x * TB;

    // ---------------- setup ----------------
    build_bfrag(sm, tid, 0, Whh_e, (const float*)0, Wih_e, bih_e, bhh_e);

    float* xs = (float*)(sm + OFF_X);
    for (int i = tid; i < TB * 2 * ENC_T; i += NTH) {
        int row = i / 40;
        xs[i] = (b0 + row < Btot) ? traj[(size_t)b0 * 40 + i] : 0.f;
    }
    // zero h cols 0-63 of buf0 (both parts)
    for (int i = tid; i < 2 * 128 * 64; i += NTH) {
        int col = i & 63, row = (i >> 6) & 127, part = i >> 13;
        *(unsigned short*)(sm + OFF_HA + part*HA_PART + (row*AROW + col)*2) = 0;
    }
    // cols 64-79, both bufs, both parts: zero; col 66 hi-part = 1.0 (bias row)
    for (int i = tid; i < 2 * 2 * 128 * 16; i += NTH) {
        int col = 64 + (i & 15), row = (i >> 4) & 127;
        int part = (i >> 11) & 1, buf = (i >> 12) & 1;
        unsigned short v = (col == 66 && part == 0) ? 0x3F80u : 0u;  // bf16(1.0)
        *(unsigned short*)(sm + OFF_HA + buf*HA_BUF + part*HA_PART + (row*AROW + col)*2) = v;
    }
    // x_0 into buf0 (direct from gmem, no x_s dependency)
    if (tid < 2 * TB) {
        int row = tid >> 1, sel = tid & 1;
        float v = (b0 + row < Btot) ? traj[(size_t)(b0 + row) * 40 + sel] : 0.f;
        store_xcol(sm, 0, row, sel, v);
    }
    if (tid < 128) ((float*)(sm + OFF_WPOS))[tid] = Wpos[tid];
    if (tid < 2)   ((float*)(sm + OFF_BPOS))[tid] = bpos[tid];

    float c[2][2][4];
    #pragma unroll
    for (int a = 0; a < 2; a++)
        #pragma unroll
        for (int h = 0; h < 2; h++)
            #pragma unroll
            for (int m = 0; m < 4; m++) c[a][h][m] = 0.f;

    const u32 smbase = (u32)__cvta_generic_to_shared(sm);
    // ldmatrix per-lane base: row-within-16 + k-offset component
    const int lrow = (lane & 7) + ((lane >> 3) & 1) * 8;
    const u32 ldm0 = (u32)(((wm * 32 + lrow) * AROW + (lane >> 4) * 8) * 2);

    __syncthreads();

    // ---------------- 50 recurrent steps ----------------
    for (int s = 0; s < TOT_T; s++) {
        const int rbuf = s & 1, wbuf = rbuf ^ 1;

        if (s == ENC_T) {   // rebuild B for decoder (fused Wih+Whh, x rows = 0)
            build_bfrag(sm, tid, 1, Wih_d, Whh_d, (const float*)0, bih_d, bhh_d);
            __syncthreads();
        }

        // emit decoder output of previous step (h_{s-1} lives in rbuf, stable all step)
        if (s >= ENC_T + 1 && tid < 2 * TB) {
            int row = tid >> 1, j = tid & 1;
            if (b0 + row < Btot) {
                const __nv_bfloat162* ph = (const __nv_bfloat162*)(sm + OFF_HA + rbuf*HA_BUF + row*AROW*2);
                const __nv_bfloat162* pl = (const __nv_bfloat162*)((const char*)ph + HA_PART);
                const float* wp = (const float*)(sm + OFF_WPOS) + j * 64;
                float a = ((const float*)(sm + OFF_BPOS))[j];
                #pragma unroll
                for (int u2 = 0; u2 < 32; u2++) {
                    __nv_bfloat162 hv = ph[u2], lv = pl[u2];
                    a += (__bfloat162float(hv.x) + __bfloat162float(lv.x)) * wp[2*u2];
                    a += (__bfloat162float(hv.y) + __bfloat162float(lv.y)) * wp[2*u2+1];
                }
                out[(size_t)(b0 + row) * (2*DEC_T) + (s - ENC_T - 1) * 2 + j] = a;
            }
        }

        // ---- GEMM: acc[128x256] = Ahi*Bhi + Ahi*Blo + Alo*Bhi ----
        float acc[2][8][4];
        #pragma unroll
        for (int ma = 0; ma < 2; ma++)
            #pragma unroll
            for (int na = 0; na < 8; na++)
                #pragma unroll
                for (int e = 0; e < 4; e++) acc[ma][na][e] = 0.f;

        const u32 ha_hi = smbase + OFF_HA + (u32)rbuf * HA_BUF + ldm0;
        const u64* __restrict__ bhi = (const u64*)(sm + OFF_BHI);
        const u64* __restrict__ blo = (const u64*)(sm + OFF_BLO);

        #pragma unroll
        for (int ks = 0; ks < NKS; ks++) {
            const int bix = ((ks * 4 + wn) * 8) * 32 + lane;
            u32 ahi0[4], ahi1[4];
            ldm4(ahi0, ha_hi + (u32)((0*16*AROW + ks*16) * 2));
            ldm4(ahi1, ha_hi + (u32)((16*AROW   + ks*16) * 2));
            #pragma unroll
            for (int na = 0; na < 8; na++) {
                u64 vh = bhi[bix + na*32], vl = blo[bix + na*32];
                u32 bh0 = (u32)vh, bh1 = (u32)(vh >> 32);
                u32 bl0 = (u32)vl, bl1 = (u32)(vl >> 32);
                mma16816(acc[0][na], ahi0, bh0, bh1);
                mma16816(acc[1][na], ahi1, bh0, bh1);
                mma16816(acc[0][na], ahi0, bl0, bl1);
                mma16816(acc[1][na], ahi1, bl0, bl1);
            }
            u32 alo0[4], alo1[4];
            ldm4(alo0, ha_hi + HA_PART + (u32)((0*16*AROW + ks*16) * 2));
            ldm4(alo1, ha_hi + HA_PART + (u32)((16*AROW   + ks*16) * 2));
            #pragma unroll
            for (int na = 0; na < 8; na++) {
                u64 vh = bhi[bix + na*32];
                u32 bh0 = (u32)vh, bh1 = (u32)(vh >> 32);
                mma16816(acc[0][na], alo0, bh0, bh1);
                mma16816(acc[1][na], alo1, bh0, bh1);
            }
        }

        // ---- epilogue: all 4 gates of each (row,unit) are local to this thread ----
        #pragma unroll
        for (int ma = 0; ma < 2; ma++)
            #pragma unroll
            for (int half = 0; half < 2; half++) {
                float hv[4];
                unsigned short hb[4], lb[4];
                #pragma unroll
                for (int m = 0; m < 4; m++) {
                    float gi = acc[ma][2*m  ][half*2 + 0];
                    float gf = acc[ma][2*m  ][half*2 + 1];
                    float gg = acc[ma][2*m+1][half*2 + 0];
                    float go = acc[ma][2*m+1][half*2 + 1];
                    float cn = sigm(gf) * c[ma][half][m] + sigm(gi) * tanh_f(gg);
                    c[ma][half][m] = cn;
                    hv[m] = sigm(go) * tanh_f(cn);
                    split_bf16(hv[m], hb[m], lb[m]);
                }
                int row  = wm*32 + ma*16 + quad + half*8;
                int colb = (wn*16 + tq*4) * 2;
                char* ph = sm + OFF_HA + wbuf*HA_BUF + row*AROW*2 + colb;
                uint2 vhi, vlo;
                vhi.x = (u32)hb[0] | ((u32)hb[1] << 16);
                vhi.y = (u32)hb[2] | ((u32)hb[3] << 16);
                vlo.x = (u32)lb[0] | ((u32)lb[1] << 16);
                vlo.y = (u32)lb[2] | ((u32)lb[3] << 16);
                *(uint2*)ph             = vhi;
                *(uint2*)(ph + HA_PART) = vlo;
            }

        // stage x_{s+1} into the write buffer (encoder only)
        if (s + 1 < ENC_T && tid < 2 * TB) {
            int row = tid >> 1, sel = tid & 1;
            store_xcol(sm, wbuf, row, sel, xs[row*40 + (s+1)*2 + sel]);
        }
        __syncthreads();
    }

    // final decoder output (h_29 is in buf[TOT_T & 1] = buf0)
    if (tid < 2 * TB) {
        int row = tid >> 1, j = tid & 1;
        if (b0 + row < Btot) {
            const int fb = TOT_T & 1;
            const __nv_bfloat162* ph = (const __nv_bfloat162*)(sm + OFF_HA + fb*HA_BUF + row*AROW*2);
            const __nv_bfloat162* pl = (const __nv_bfloat162*)((const char*)ph + HA_PART);
            const float* wp = (const float*)(sm + OFF_WPOS) + j * 64;
            float a = ((const float*)(sm + OFF_BPOS))[j];
            #pragma unroll
            for (int u2 = 0; u2 < 32; u2++) {
                __nv_bfloat162 hv = ph[u2], lv = pl[u2];
                a += (__bfloat162float(hv.x) + __bfloat162float(lv.x)) * wp[2*u2];
                a += (__bfloat162float(hv.y) + __bfloat162float(lv.y)) * wp[2*u2+1];
            }
            out[(size_t)(b0 + row) * (2*DEC_T) + (DEC_T - 1) * 2 + j] = a;
        }
    }
}

extern "C" void kernel_launch(void* const* d_in, const int* in_sizes, int n_in,
                              void* d_out, int out_size) {
    const float* traj  = (const float*)d_in[0];
    const float* Wih_e = (const float*)d_in[1];
    const float* Whh_e = (const float*)d_in[2];
    const float* bih_e = (const float*)d_in[3];
    const float* bhh_e = (const float*)d_in[4];
    const float* Wih_d = (const float*)d_in[5];
    const float* Whh_d = (const float*)d_in[6];
    const float* bih_d = (const float*)d_in[7];
    const float* bhh_d = (const float*)d_in[8];
    const float* Wpos  = (const float*)d_in[9];
    const float* bpos  = (const float*)d_in[10];
    float* out = (float*)d_out;

    int B = in_sizes[0] / (2 * ENC_T);
    int grid = (B + TB - 1) / TB;

    cudaFuncSetAttribute(lstm_mma,
                         cudaFuncAttributeMaxDynamicSharedMemorySize, SMEM_SZ);

    lstm_mma<<<grid, NTH, SMEM_SZ>>>(traj, Wih_e, Whh_e, bih_e, bhh_e,
                                     Wih_d, Whh_d, bih_d, bhh_d,
                                     Wpos, bpos, out, B);
}

// round 11
// speedup vs baseline: 2.5972x; 1.1017x over previous
#include <cuda_runtime.h>
#include <cuda_bf16.h>

#define HID    64
#define ENC_T  20
#define DEC_T  30
#define TB     128
#define NTH    512
#define AROW   88           // bf16 cols per row of A/h buffer (bank-disjoint stride)
#define TOT_T  (ENC_T + DEC_T)

typedef unsigned int u32;
typedef unsigned long long u64;

// ---- smem byte offsets ----
#define OFF_BHI   0                       // B frags hi: 5120 u64 = 40960 B
#define OFF_BLO   40960                   // B frags lo: 40960 B
#define OFF_HA    81920                   // h/A: 2 bufs x 2 parts x 128 x 88 bf16
#define HA_BUF    45056
#define HA_PART   22528
#define OFF_X     (OFF_HA + 2*HA_BUF)     // x: 128 x 40 f32 = 20480 B
#define OFF_WPOS  (OFF_X + 128*40*4)      // 128 f32
#define OFF_BPOS  (OFF_WPOS + 128*4)      // 2 f32
#define OFF_BTAB  (OFF_BPOS + 16)         // decoder bias table: 256 f32
#define SMEM_SZ   (OFF_BTAB + 1024)

// ---- activations: HW tanh (sm_75+), sigmoid via tanh ----
__device__ __forceinline__ float tanh_hw(float x) {
    float y; asm("tanh.approx.f32 %0, %1;" : "=f"(y) : "f"(x)); return y;
}
__device__ __forceinline__ float sigm(float x) {
    return fmaf(0.5f, tanh_hw(0.5f * x), 0.5f);
}

// ---- mma / ldmatrix wrappers ----
__device__ __forceinline__ void mma16816(float* d, const u32* a, u32 b0, u32 b1) {
    asm("mma.sync.aligned.m16n8k16.row.col.f32.bf16.bf16.f32 "
        "{%0,%1,%2,%3}, {%4,%5,%6,%7}, {%8,%9}, {%0,%1,%2,%3};"
        : "+f"(d[0]), "+f"(d[1]), "+f"(d[2]), "+f"(d[3])
        : "r"(a[0]), "r"(a[1]), "r"(a[2]), "r"(a[3]), "r"(b0), "r"(b1));
}
__device__ __forceinline__ void ldm4(u32* r, u32 addr) {
    asm volatile("ldmatrix.sync.aligned.m8n8.x4.shared.b16 {%0,%1,%2,%3}, [%4];"
        : "=r"(r[0]), "=r"(r[1]), "=r"(r[2]), "=r"(r[3]) : "r"(addr));
}

__device__ __forceinline__ void split_bf16(float v, unsigned short& hb, unsigned short& lb) {
    __nv_bfloat16 hi = __float2bfloat16_rn(v);
    __nv_bfloat16 lo = __float2bfloat16_rn(v - __bfloat162float(hi));
    hb = __bfloat16_as_ushort(hi);
    lb = __bfloat16_as_ushort(lo);
}

// Build B fragments (exact mma layout). phase 0 = encoder (5 ks, x+bias rows),
// phase 1 = decoder (4 ks, pure fused weights).
__device__ __forceinline__ void build_bfrag(char* sm, int tid, int phase,
        const float* __restrict__ W, const float* __restrict__ W2,
        const float* __restrict__ Wx,
        const float* __restrict__ b1v, const float* __restrict__ b2v)
{
    u64* bhi = (u64*)(sm + OFF_BHI);
    u64* blo = (u64*)(sm + OFF_BLO);
    const int nfr = phase ? 4096 : 5120;
    for (int idx = tid; idx < nfr; idx += NTH) {
        int ks = idx >> 10, wn = (idx >> 8) & 3, na = (idx >> 5) & 7, T = idx & 31;
        int cc = T >> 2, tq = T & 3;
        int unit = wn * 16 + ((cc >> 1) << 2) + (na >> 1);
        int gate = ((na & 1) << 1) | (cc & 1);
        int grow = gate * 64 + unit;
        u32 phi[2] = {0, 0}, plo[2] = {0, 0};
        #pragma unroll
        for (int i = 0; i < 2; i++)
            #pragma unroll
            for (int e = 0; e < 2; e++) {
                int k = ks * 16 + tq * 2 + e + 8 * i;
                float v = 0.f;
                if (k < 64)       v = phase ? (W[grow*64+k] + W2[grow*64+k]) : W[grow*64+k];
                else if (k < 66)  v = phase ? 0.f : Wx[grow*2 + (k-64)];
                else if (k == 66) v = phase ? 0.f : (b1v[grow] + b2v[grow]);
                unsigned short hb, lb;
                split_bf16(v, hb, lb);
                phi[i] |= (u32)hb << (16 * e);
                plo[i] |= (u32)lb << (16 * e);
            }
        bhi[idx] = (u64)phi[0] | ((u64)phi[1] << 32);
        blo[idx] = (u64)plo[0] | ((u64)plo[1] << 32);
    }
}

__device__ __forceinline__ void store_xcol(char* sm, int buf, int row, int sel, float v) {
    unsigned short hb, lb;
    split_bf16(v, hb, lb);
    *(unsigned short*)(sm + OFF_HA + buf*HA_BUF + 0*HA_PART + (row*AROW + 64 + sel)*2) = hb;
    *(unsigned short*)(sm + OFF_HA + buf*HA_BUF + 1*HA_PART + (row*AROW + 64 + sel)*2) = lb;
}

// decoder output: all 512 threads; pair (tid, tid^1) split one 64-dot, shfl-combined
__device__ __forceinline__ void emit_out(char* sm, int tid, int buf, int b0, int Btot,
                                         float* __restrict__ out, int tstep) {
    const int half = tid & 1, p = tid >> 1;
    const int row = p >> 1, j = p & 1;
    const __nv_bfloat162* ph = (const __nv_bfloat162*)(sm + OFF_HA + buf*HA_BUF + row*AROW*2);
    const __nv_bfloat162* pl = (const __nv_bfloat162*)((const char*)ph + HA_PART);
    const float2* wp2 = (const float2*)((const float*)(sm + OFF_WPOS) + j*64);
    float a = 0.f;
    #pragma unroll
    for (int i = 0; i < 16; i++) {
        int u2 = half * 16 + i;
        __nv_bfloat162 hv = ph[u2], lv = pl[u2];
        float2 w = wp2[u2];
        a += (__bfloat162float(hv.x) + __bfloat162float(lv.x)) * w.x
           + (__bfloat162float(hv.y) + __bfloat162float(lv.y)) * w.y;
    }
    a += __shfl_xor_sync(0xFFFFFFFFu, a, 1);
    if (half == 0 && b0 + row < Btot)
        out[(size_t)(b0 + row) * (2*DEC_T) + tstep*2 + j]
            = a + ((const float*)(sm + OFF_BPOS))[j];
}

__global__ void __launch_bounds__(NTH, 1)
lstm_mma(const float* __restrict__ traj,
         const float* __restrict__ Wih_e, const float* __restrict__ Whh_e,
         const float* __restrict__ bih_e, const float* __restrict__ bhh_e,
         const float* __restrict__ Wih_d, const float* __restrict__ Whh_d,
         const float* __restrict__ bih_d, const float* __restrict__ bhh_d,
         const float* __restrict__ Wpos,  const float* __restrict__ bpos,
         float* __restrict__ out, int Btot)
{
    extern __shared__ char sm[];
    const int tid  = threadIdx.x;
    const int lane = tid & 31, warp = tid >> 5;
    const int wm   = warp >> 2, wn = warp & 3;
    const int quad = lane >> 2, tq = lane & 3;
    const int b0   = blockIdx.x * TB;

    // ---------------- setup ----------------
    build_bfrag(sm, tid, 0, Whh_e, (const float*)0, Wih_e, bih_e, bhh_e);

    float* xs = (float*)(sm + OFF_X);
    for (int i = tid; i < TB * 2 * ENC_T; i += NTH) {
        int row = i / 40;
        xs[i] = (b0 + row < Btot) ? traj[(size_t)b0 * 40 + i] : 0.f;
    }
    for (int i = tid; i < 2 * 128 * 64; i += NTH) {
        int col = i & 63, row = (i >> 6) & 127, part = i >> 13;
        *(unsigned short*)(sm + OFF_HA + part*HA_PART + (row*AROW + col)*2) = 0;
    }
    for (int i = tid; i < 2 * 2 * 128 * 16; i += NTH) {
        int col = 64 + (i & 15), row = (i >> 4) & 127;
        int part = (i >> 11) & 1, buf = (i >> 12) & 1;
        unsigned short v = (col == 66 && part == 0) ? 0x3F80u : 0u;
        *(unsigned short*)(sm + OFF_HA + buf*HA_BUF + part*HA_PART + (row*AROW + col)*2) = v;
    }
    if (tid < 2 * TB) {
        int row = tid >> 1, sel = tid & 1;
        float v = (b0 + row < Btot) ? traj[(size_t)(b0 + row) * 40 + sel] : 0.f;
        store_xcol(sm, 0, row, sel, v);
    }
    if (tid < 128) ((float*)(sm + OFF_WPOS))[tid] = Wpos[tid];
    if (tid < 2)   ((float*)(sm + OFF_BPOS))[tid] = bpos[tid];

    float c[2][2][4];
    #pragma unroll
    for (int a = 0; a < 2; a++)
        #pragma unroll
        for (int h = 0; h < 2; h++)
            #pragma unroll
            for (int m = 0; m < 4; m++) c[a][h][m] = 0.f;

    const u32 smbase = (u32)__cvta_generic_to_shared(sm);
    const int lrow = (lane & 7) + ((lane >> 3) & 1) * 8;
    const u32 ldm0 = (u32)(((wm * 32 + lrow) * AROW + (lane >> 4) * 8) * 2);

    __syncthreads();

    // ================ encoder: 20 steps, K = 80 (5 k-steps) ================
    for (int s = 0; s < ENC_T; s++) {
        const int rbuf = s & 1, wbuf = rbuf ^ 1;

        float acc[2][8][4];
        #pragma unroll
        for (int ma = 0; ma < 2; ma++)
            #pragma unroll
            for (int na = 0; na < 8; na++)
                #pragma unroll
                for (int e = 0; e < 4; e++) acc[ma][na][e] = 0.f;

        const u32 ha_hi = smbase + OFF_HA + (u32)rbuf * HA_BUF + ldm0;
        const u64* __restrict__ bhi = (const u64*)(sm + OFF_BHI);
        const u64* __restrict__ blo = (const u64*)(sm + OFF_BLO);

        #pragma unroll
        for (int ks = 0; ks < 5; ks++) {
            const int bix = ((ks * 4 + wn) * 8) * 32 + lane;
            u32 ahi0[4], ahi1[4];
            ldm4(ahi0, ha_hi + (u32)((ks*16) * 2));
            ldm4(ahi1, ha_hi + (u32)((16*AROW + ks*16) * 2));
            #pragma unroll
            for (int na = 0; na < 8; na++) {
                u64 vh = bhi[bix + na*32], vl = blo[bix + na*32];
                u32 bh0 = (u32)vh, bh1 = (u32)(vh >> 32);
                u32 bl0 = (u32)vl, bl1 = (u32)(vl >> 32);
                mma16816(acc[0][na], ahi0, bh0, bh1);
                mma16816(acc[1][na], ahi1, bh0, bh1);
                mma16816(acc[0][na], ahi0, bl0, bl1);
                mma16816(acc[1][na], ahi1, bl0, bl1);
            }
            u32 alo0[4], alo1[4];
            ldm4(alo0, ha_hi + HA_PART + (u32)((ks*16) * 2));
            ldm4(alo1, ha_hi + HA_PART + (u32)((16*AROW + ks*16) * 2));
            #pragma unroll
            for (int na = 0; na < 8; na++) {
                u64 vh = bhi[bix + na*32];
                u32 bh0 = (u32)vh, bh1 = (u32)(vh >> 32);
                mma16816(acc[0][na], alo0, bh0, bh1);
                mma16816(acc[1][na], alo1, bh0, bh1);
            }
        }

        #pragma unroll
        for (int ma = 0; ma < 2; ma++)
            #pragma unroll
            for (int half = 0; half < 2; half++) {
                unsigned short hb[4], lb[4];
                #pragma unroll
                for (int m = 0; m < 4; m++) {
                    float gi = acc[ma][2*m  ][half*2 + 0];
                    float gf = acc[ma][2*m  ][half*2 + 1];
                    float gg = acc[ma][2*m+1][half*2 + 0];
                    float go = acc[ma][2*m+1][half*2 + 1];
                    float cn = sigm(gf) * c[ma][half][m] + sigm(gi) * tanh_hw(gg);
                    c[ma][half][m] = cn;
                    split_bf16(sigm(go) * tanh_hw(cn), hb[m], lb[m]);
                }
                int row  = wm*32 + ma*16 + quad + half*8;
                int colb = (wn*16 + tq*4) * 2;
                char* ph = sm + OFF_HA + wbuf*HA_BUF + row*AROW*2 + colb;
                uint2 vhi, vlo;
                vhi.x = (u32)hb[0] | ((u32)hb[1] << 16);
                vhi.y = (u32)hb[2] | ((u32)hb[3] << 16);
                vlo.x = (u32)lb[0] | ((u32)lb[1] << 16);
                vlo.y = (u32)lb[2] | ((u32)lb[3] << 16);
                *(uint2*)ph             = vhi;
                *(uint2*)(ph + HA_PART) = vlo;
            }

        if (s + 1 < ENC_T && tid < 2 * TB) {
            int row = tid >> 1, sel = tid & 1;
            store_xcol(sm, wbuf, row, sel, xs[row*40 + (s+1)*2 + sel]);
        }
        __syncthreads();
    }

    // ---- rebuild B for decoder (fused Wih+Whh, 4 k-steps) + bias table ----
    build_bfrag(sm, tid, 1, Wih_d, Whh_d, (const float*)0, (const float*)0, (const float*)0);
    {
        float* btab = (float*)(sm + OFF_BTAB);
        for (int i = tid; i < 256; i += NTH) {
            int wn_ = i >> 6, tq_ = (i >> 4) & 3, na_ = (i >> 1) & 7, par = i & 1;
            int unit = wn_*16 + tq_*4 + (na_ >> 1);
            int gate = ((na_ & 1) << 1) | par;
            int grow = gate * 64 + unit;
            btab[i] = bih_d[grow] + bhh_d[grow];
        }
    }
    __syncthreads();

    // ================ decoder: 30 steps, K = 64 (4 k-steps), bias in acc ================
    for (int d = 0; d < DEC_T; d++) {
        const int s = ENC_T + d;
        const int rbuf = s & 1, wbuf = rbuf ^ 1;

        if (d >= 1) emit_out(sm, tid, rbuf, b0, Btot, out, d - 1);

        float acc[2][8][4];
        {
            const float4* bt4 = (const float4*)((const float*)(sm + OFF_BTAB) + ((wn*4 + tq) << 4));
            float bvv[16];
            *(float4*)(bvv+ 0) = bt4[0];
            *(float4*)(bvv+ 4) = bt4[1];
            *(float4*)(bvv+ 8) = bt4[2];
            *(float4*)(bvv+12) = bt4[3];
            #pragma unroll
            for (int na = 0; na < 8; na++) {
                float b0v = bvv[na*2], b1v = bvv[na*2+1];
                acc[0][na][0] = b0v; acc[0][na][1] = b1v;
                acc[0][na][2] = b0v; acc[0][na][3] = b1v;
                acc[1][na][0] = b0v; acc[1][na][1] = b1v;
                acc[1][na][2] = b0v; acc[1][na][3] = b1v;
            }
        }

        const u32 ha_hi = smbase + OFF_HA + (u32)rbuf * HA_BUF + ldm0;
        const u64* __restrict__ bhi = (const u64*)(sm + OFF_BHI);
        const u64* __restrict__ blo = (const u64*)(sm + OFF_BLO);

        #pragma unroll
        for (int ks = 0; ks < 4; ks++) {
            const int bix = ((ks * 4 + wn) * 8) * 32 + lane;
            u32 ahi0[4], ahi1[4];
            ldm4(ahi0, ha_hi + (u32)((ks*16) * 2));
            ldm4(ahi1, ha_hi + (u32)((16*AROW + ks*16) * 2));
            #pragma unroll
            for (int na = 0; na < 8; na++) {
                u64 vh = bhi[bix + na*32], vl = blo[bix + na*32];
                u32 bh0 = (u32)vh, bh1 = (u32)(vh >> 32);
                u32 bl0 = (u32)vl, bl1 = (u32)(vl >> 32);
                mma16816(acc[0][na], ahi0, bh0, bh1);
                mma16816(acc[1][na], ahi1, bh0, bh1);
                mma16816(acc[0][na], ahi0, bl0, bl1);
                mma16816(acc[1][na], ahi1, bl0, bl1);
            }
            u32 alo0[4], alo1[4];
            ldm4(alo0, ha_hi + HA_PART + (u32)((ks*16) * 2));
            ldm4(alo1, ha_hi + HA_PART + (u32)((16*AROW + ks*16) * 2));
            #pragma unroll
            for (int na = 0; na < 8; na++) {
                u64 vh = bhi[bix + na*32];
                u32 bh0 = (u32)vh, bh1 = (u32)(vh >> 32);
                mma16816(acc[0][na], alo0, bh0, bh1);
                mma16816(acc[1][na], alo1, bh0, bh1);
            }
        }

        #pragma unroll
        for (int ma = 0; ma < 2; ma++)
            #pragma unroll
            for (int half = 0; half < 2; half++) {
                unsigned short hb[4], lb[4];
                #pragma unroll
                for (int m = 0; m < 4; m++) {
                    float gi = acc[ma][2*m  ][half*2 + 0];
                    float gf = acc[ma][2*m  ][half*2 + 1];
                    float gg = acc[ma][2*m+1][half*2 + 0];
                    float go = acc[ma][2*m+1][half*2 + 1];
                    float cn = sigm(gf) * c[ma][half][m] + sigm(gi) * tanh_hw(gg);
                    c[ma][half][m] = cn;
                    split_bf16(sigm(go) * tanh_hw(cn), hb[m], lb[m]);
                }
                int row  = wm*32 + ma*16 + quad + half*8;
                int colb = (wn*16 + tq*4) * 2;
                char* ph = sm + OFF_HA + wbuf*HA_BUF + row*AROW*2 + colb;
                uint2 vhi, vlo;
                vhi.x = (u32)hb[0] | ((u32)hb[1] << 16);
                vhi.y = (u32)hb[2] | ((u32)hb[3] << 16);
                vlo.x = (u32)lb[0] | ((u32)lb[1] << 16);
                vlo.y = (u32)lb[2] | ((u32)lb[3] << 16);
                *(uint2*)ph             = vhi;
                *(uint2*)(ph + HA_PART) = vlo;
            }
        __syncthreads();
    }

    // final output (h_29 lives in buf[TOT_T & 1] = buf0)
    emit_out(sm, tid, TOT_T & 1, b0, Btot, out, DEC_T - 1);
}

extern "C" void kernel_launch(void* const* d_in, const int* in_sizes, int n_in,
                              void* d_out, int out_size) {
    const float* traj  = (const float*)d_in[0];
    const float* Wih_e = (const float*)d_in[1];
    const float* Whh_e = (const float*)d_in[2];
    const float* bih_e = (const float*)d_in[3];
    const float* bhh_e = (const float*)d_in[4];
    const float* Wih_d = (const float*)d_in[5];
    const float* Whh_d = (const float*)d_in[6];
    const float* bih_d = (const float*)d_in[7];
    const float* bhh_d = (const float*)d_in[8];
    const float* Wpos  = (const float*)d_in[9];
    const float* bpos  = (const float*)d_in[10];
    float* out = (float*)d_out;

    int B = in_sizes[0] / (2 * ENC_T);
    int grid = (B + TB - 1) / TB;

    cudaFuncSetAttribute(lstm_mma,
                         cudaFuncAttributeMaxDynamicSharedMemorySize, SMEM_SZ);

    lstm_mma<<<grid, NTH, SMEM_SZ>>>(traj, Wih_e, Whh_e, bih_e, bhh_e,
                                     Wih_d, Whh_d, bih_d, bhh_d,
                                     Wpos, bpos, out, B);
}

// round 14
// speedup vs baseline: 2.6811x; 1.0323x over previous
#include <cuda_runtime.h>
#include <cuda_bf16.h>

#define HID    64
#define ENC_T  20
#define DEC_T  30
#define TB     128
#define NTH    512
#define AROW   88           // bf16 cols per row of A/h buffer (bank-disjoint stride)
#define TOT_T  (ENC_T + DEC_T)

typedef unsigned int u32;
typedef unsigned long long u64;

// ---- smem byte offsets ----
#define OFF_BHI   0                       // B frags hi: 5120 u64 = 40960 B
#define OFF_BLO   40960                   // B frags lo: 40960 B
#define OFF_HA    81920                   // h/A: 2 bufs x 2 parts x 128 x 88 bf16
#define HA_BUF    45056
#define HA_PART   22528
#define OFF_X     (OFF_HA + 2*HA_BUF)     // x: 128 x 40 f32 = 20480 B
#define OFF_WPOS  (OFF_X + 128*40*4)      // 128 f32
#define OFF_BPOS  (OFF_WPOS + 128*4)      // 2 f32
#define OFF_BTAB  (OFF_BPOS + 16)         // decoder bias table: 256 f32
#define SMEM_SZ   (OFF_BTAB + 1024)

// per-half named barrier (id 1 or 2, 256 threads each)
#define HBAR(grp) asm volatile("bar.sync %0, %1;" :: "r"((grp) + 1), "r"(256) : "memory")

// ---- activations: HW tanh (sm_75+), sigmoid via tanh ----
__device__ __forceinline__ float tanh_hw(float x) {
    float y; asm("tanh.approx.f32 %0, %1;" : "=f"(y) : "f"(x)); return y;
}
__device__ __forceinline__ float sigm(float x) {
    return fmaf(0.5f, tanh_hw(0.5f * x), 0.5f);
}

// ---- mma / ldmatrix wrappers ----
__device__ __forceinline__ void mma16816(float* d, const u32* a, u32 b0, u32 b1) {
    asm("mma.sync.aligned.m16n8k16.row.col.f32.bf16.bf16.f32 "
        "{%0,%1,%2,%3}, {%4,%5,%6,%7}, {%8,%9}, {%0,%1,%2,%3};"
        : "+f"(d[0]), "+f"(d[1]), "+f"(d[2]), "+f"(d[3])
        : "r"(a[0]), "r"(a[1]), "r"(a[2]), "r"(a[3]), "r"(b0), "r"(b1));
}
__device__ __forceinline__ void ldm4(u32* r, u32 addr) {
    asm volatile("ldmatrix.sync.aligned.m8n8.x4.shared.b16 {%0,%1,%2,%3}, [%4];"
        : "=r"(r[0]), "=r"(r[1]), "=r"(r[2]), "=r"(r[3]) : "r"(addr));
}

__device__ __forceinline__ void split_bf16(float v, unsigned short& hb, unsigned short& lb) {
    __nv_bfloat16 hi = __float2bfloat16_rn(v);
    __nv_bfloat16 lo = __float2bfloat16_rn(v - __bfloat162float(hi));
    hb = __bfloat16_as_ushort(hi);
    lb = __bfloat16_as_ushort(lo);
}

// Build B fragments (exact mma layout). phase 0 = encoder (5 ks, x+bias rows),
// phase 1 = decoder (4 ks, pure fused weights).
__device__ void build_bfrag(char* sm, int tid, int phase,
        const float* __restrict__ W, const float* __restrict__ W2,
        const float* __restrict__ Wx,
        const float* __restrict__ b1v, const float* __restrict__ b2v)
{
    u64* bhi = (u64*)(sm + OFF_BHI);
    u64* blo = (u64*)(sm + OFF_BLO);
    const int nfr = phase ? 4096 : 5120;
    for (int idx = tid; idx < nfr; idx += NTH) {
        int ks = idx >> 10, wn = (idx >> 8) & 3, na = (idx >> 5) & 7, T = idx & 31;
        int cc = T >> 2, tq = T & 3;
        int unit = wn * 16 + ((cc >> 1) << 2) + (na >> 1);
        int gate = ((na & 1) << 1) | (cc & 1);
        int grow = gate * 64 + unit;
        u32 phi[2] = {0, 0}, plo[2] = {0, 0};
        #pragma unroll
        for (int i = 0; i < 2; i++)
            #pragma unroll
            for (int e = 0; e < 2; e++) {
                int k = ks * 16 + tq * 2 + e + 8 * i;
                float v = 0.f;
                if (k < 64)       v = phase ? (W[grow*64+k] + W2[grow*64+k]) : W[grow*64+k];
                else if (k < 66)  v = phase ? 0.f : Wx[grow*2 + (k-64)];
                else if (k == 66) v = phase ? 0.f : (b1v[grow] + b2v[grow]);
                unsigned short hb, lb;
                split_bf16(v, hb, lb);
                phi[i] |= (u32)hb << (16 * e);
                plo[i] |= (u32)lb << (16 * e);
            }
        bhi[idx] = (u64)phi[0] | ((u64)phi[1] << 32);
        blo[idx] = (u64)plo[0] | ((u64)plo[1] << 32);
    }
}

__device__ __forceinline__ void store_xcol(char* sm, int buf, int row, int sel, float v) {
    unsigned short hb, lb;
    split_bf16(v, hb, lb);
    *(unsigned short*)(sm + OFF_HA + buf*HA_BUF + 0*HA_PART + (row*AROW + 64 + sel)*2) = hb;
    *(unsigned short*)(sm + OFF_HA + buf*HA_BUF + 1*HA_PART + (row*AROW + 64 + sel)*2) = lb;
}

// decoder output: each half's 256 threads cover its 64 rows; pair (t, t^1)
// splits one 64-dot, shfl-combined
__device__ __forceinline__ void emit_out(char* sm, int tid, int buf, int b0, int Btot,
                                         float* __restrict__ out, int tstep) {
    const int grp  = tid >> 8;
    const int loc  = tid & 255;
    const int hd   = loc & 1, p = loc >> 1;
    const int row  = grp * 64 + (p >> 1), j = p & 1;
    const __nv_bfloat162* ph = (const __nv_bfloat162*)(sm + OFF_HA + buf*HA_BUF + row*AROW*2);
    const __nv_bfloat162* pl = (const __nv_bfloat162*)((const char*)ph + HA_PART);
    const float2* wp2 = (const float2*)((const float*)(sm + OFF_WPOS) + j*64);
    float a = 0.f;
    #pragma unroll
    for (int i = 0; i < 16; i++) {
        int u2 = hd * 16 + i;
        __nv_bfloat162 hv = ph[u2], lv = pl[u2];
        float2 w = wp2[u2];
        a += (__bfloat162float(hv.x) + __bfloat162float(lv.x)) * w.x
           + (__bfloat162float(hv.y) + __bfloat162float(lv.y)) * w.y;
    }
    a += __shfl_xor_sync(0xFFFFFFFFu, a, 1);
    if (hd == 0 && b0 + row < Btot)
        out[(size_t)(b0 + row) * (2*DEC_T) + tstep*2 + j]
            = a + ((const float*)(sm + OFF_BPOS))[j];
}

__global__ void __launch_bounds__(NTH, 1)
lstm_mma(const float* __restrict__ traj,
         const float* __restrict__ Wih_e, const float* __restrict__ Whh_e,
         const float* __restrict__ bih_e, const float* __restrict__ bhh_e,
         const float* __restrict__ Wih_d, const float* __restrict__ Whh_d,
         const float* __restrict__ bih_d, const float* __restrict__ bhh_d,
         const float* __restrict__ Wpos,  const float* __restrict__ bpos,
         float* __restrict__ out, int Btot)
{
    extern __shared__ char sm[];
    const int tid  = threadIdx.x;
    const int lane = tid & 31, warp = tid >> 5;
    const int grp  = warp >> 3;                 // half: rows grp*64 .. grp*64+63
    const int wm2  = (warp >> 2) & 1;           // 32-row band within the half
    const int wn   = warp & 3;                  // n-band (units wn*16)
    const int rowbase = grp * 64 + wm2 * 32;
    const int quad = lane >> 2, tq = lane & 3;
    const int b0   = blockIdx.x * TB;

    // ---------------- setup (global) ----------------
    build_bfrag(sm, tid, 0, Whh_e, (const float*)0, Wih_e, bih_e, bhh_e);

    float* xs = (float*)(sm + OFF_X);
    for (int i = tid; i < TB * 2 * ENC_T; i += NTH) {
        int row = i / 40;
        xs[i] = (b0 + row < Btot) ? traj[(size_t)b0 * 40 + i] : 0.f;
    }
    for (int i = tid; i < 2 * 128 * 64; i += NTH) {
        int col = i & 63, row = (i >> 6) & 127, part = i >> 13;
        *(unsigned short*)(sm + OFF_HA + part*HA_PART + (row*AROW + col)*2) = 0;
    }
    for (int i = tid; i < 2 * 2 * 128 * 16; i += NTH) {
        int col = 64 + (i & 15), row = (i >> 4) & 127;
        int part = (i >> 11) & 1, buf = (i >> 12) & 1;
        unsigned short v = (col == 66 && part == 0) ? 0x3F80u : 0u;
        *(unsigned short*)(sm + OFF_HA + buf*HA_BUF + part*HA_PART + (row*AROW + col)*2) = v;
    }
    if (tid < 2 * TB) {
        int row = tid >> 1, sel = tid & 1;
        float v = (b0 + row < Btot) ? traj[(size_t)(b0 + row) * 40 + sel] : 0.f;
        store_xcol(sm, 0, row, sel, v);
    }
    if (tid < 128) ((float*)(sm + OFF_WPOS))[tid] = Wpos[tid];
    if (tid < 2)   ((float*)(sm + OFF_BPOS))[tid] = bpos[tid];

    float c[2][2][4];
    #pragma unroll
    for (int a = 0; a < 2; a++)
        #pragma unroll
        for (int h = 0; h < 2; h++)
            #pragma unroll
            for (int m = 0; m < 4; m++) c[a][h][m] = 0.f;

    const u32 smbase = (u32)__cvta_generic_to_shared(sm);
    const int lrow = (lane & 7) + ((lane >> 3) & 1) * 8;
    const u32 ldm0 = (u32)(((rowbase + lrow) * AROW + (lane >> 4) * 8) * 2);
    const int xloc = tid & 255;                 // per-half staging thread index

    __syncthreads();

    // ================ encoder: 20 steps, K = 80 (5 k-steps) ================
    for (int s = 0; s < ENC_T; s++) {
        const int rbuf = s & 1, wbuf = rbuf ^ 1;

        float acc[2][8][4];
        #pragma unroll
        for (int ma = 0; ma < 2; ma++)
            #pragma unroll
            for (int na = 0; na < 8; na++)
                #pragma unroll
                for (int e = 0; e < 4; e++) acc[ma][na][e] = 0.f;

        const u32 ha_hi = smbase + OFF_HA + (u32)rbuf * HA_BUF + ldm0;
        const u64* __restrict__ bhi = (const u64*)(sm + OFF_BHI);
        const u64* __restrict__ blo = (const u64*)(sm + OFF_BLO);

        #pragma unroll
        for (int ks = 0; ks < 5; ks++) {
            const int bix = ((ks * 4 + wn) * 8) * 32 + lane;
            u32 ahi0[4], ahi1[4];
            ldm4(ahi0, ha_hi + (u32)((ks*16) * 2));
            ldm4(ahi1, ha_hi + (u32)((16*AROW + ks*16) * 2));
            #pragma unroll
            for (int na = 0; na < 8; na++) {
                u64 vh = bhi[bix + na*32], vl = blo[bix + na*32];
                u32 bh0 = (u32)vh, bh1 = (u32)(vh >> 32);
                u32 bl0 = (u32)vl, bl1 = (u32)(vl >> 32);
                mma16816(acc[0][na], ahi0, bh0, bh1);
                mma16816(acc[1][na], ahi1, bh0, bh1);
                mma16816(acc[0][na], ahi0, bl0, bl1);
                mma16816(acc[1][na], ahi1, bl0, bl1);
            }
            u32 alo0[4], alo1[4];
            ldm4(alo0, ha_hi + HA_PART + (u32)((ks*16) * 2));
            ldm4(alo1, ha_hi + HA_PART + (u32)((16*AROW + ks*16) * 2));
            #pragma unroll
            for (int na = 0; na < 8; na++) {
                u64 vh = bhi[bix + na*32];
                u32 bh0 = (u32)vh, bh1 = (u32)(vh >> 32);
                mma16816(acc[0][na], alo0, bh0, bh1);
                mma16816(acc[1][na], alo1, bh0, bh1);
            }
        }

        #pragma unroll
        for (int ma = 0; ma < 2; ma++)
            #pragma unroll
            for (int hh = 0; hh < 2; hh++) {
                unsigned short hb[4], lb[4];
                #pragma unroll
                for (int m = 0; m < 4; m++) {
                    float gi = acc[ma][2*m  ][hh*2 + 0];
                    float gf = acc[ma][2*m  ][hh*2 + 1];
                    float gg = acc[ma][2*m+1][hh*2 + 0];
                    float go = acc[ma][2*m+1][hh*2 + 1];
                    float cn = sigm(gf) * c[ma][hh][m] + sigm(gi) * tanh_hw(gg);
                    c[ma][hh][m] = cn;
                    split_bf16(sigm(go) * tanh_hw(cn), hb[m], lb[m]);
                }
                int row  = rowbase + ma*16 + quad + hh*8;
                int colb = (wn*16 + tq*4) * 2;
                char* ph = sm + OFF_HA + wbuf*HA_BUF + row*AROW*2 + colb;
                uint2 vhi, vlo;
                vhi.x = (u32)hb[0] | ((u32)hb[1] << 16);
                vhi.y = (u32)hb[2] | ((u32)hb[3] << 16);
                vlo.x = (u32)lb[0] | ((u32)lb[1] << 16);
                vlo.y = (u32)lb[2] | ((u32)lb[3] << 16);
                *(uint2*)ph             = vhi;
                *(uint2*)(ph + HA_PART) = vlo;
            }

        if (s + 1 < ENC_T && xloc < 128) {
            int row = grp * 64 + (xloc >> 1), sel = xloc & 1;
            store_xcol(sm, wbuf, row, sel, xs[row*40 + (s+1)*2 + sel]);
        }
        HBAR(grp);
    }

    // ---- decoder transition (global): rebuild B (fused Wih+Whh) + bias table ----
    __syncthreads();
    build_bfrag(sm, tid, 1, Wih_d, Whh_d, (const float*)0, (const float*)0, (const float*)0);
    {
        float* btab = (float*)(sm + OFF_BTAB);
        for (int i = tid; i < 256; i += NTH) {
            int wn_ = i >> 6, tq_ = (i >> 4) & 3, na_ = (i >> 1) & 7, par = i & 1;
            int unit = wn_*16 + tq_*4 + (na_ >> 1);
            int gate = ((na_ & 1) << 1) | par;
            int grow = gate * 64 + unit;
            btab[i] = bih_d[grow] + bhh_d[grow];
        }
    }
    __syncthreads();

    // ================ decoder: 30 steps, K = 64 (4 k-steps), bias in acc ================
    for (int d = 0; d < DEC_T; d++) {
        const int s = ENC_T + d;
        const int rbuf = s & 1, wbuf = rbuf ^ 1;

        if (d >= 1) emit_out(sm, tid, rbuf, b0, Btot, out, d - 1);

        float acc[2][8][4];
        {
            const float4* bt4 = (const float4*)((const float*)(sm + OFF_BTAB) + ((wn*4 + tq) << 4));
            float bvv[16];
            *(float4*)(bvv+ 0) = bt4[0];
            *(float4*)(bvv+ 4) = bt4[1];
            *(float4*)(bvv+ 8) = bt4[2];
            *(float4*)(bvv+12) = bt4[3];
            #pragma unroll
            for (int na = 0; na < 8; na++) {
                float b0v = bvv[na*2], b1v = bvv[na*2+1];
                acc[0][na][0] = b0v; acc[0][na][1] = b1v;
                acc[0][na][2] = b0v; acc[0][na][3] = b1v;
                acc[1][na][0] = b0v; acc[1][na][1] = b1v;
                acc[1][na][2] = b0v; acc[1][na][3] = b1v;
            }
        }

        const u32 ha_hi = smbase + OFF_HA + (u32)rbuf * HA_BUF + ldm0;
        const u64* __restrict__ bhi = (const u64*)(sm + OFF_BHI);
        const u64* __restrict__ blo = (const u64*)(sm + OFF_BLO);

        #pragma unroll
        for (int ks = 0; ks < 4; ks++) {
            const int bix = ((ks * 4 + wn) * 8) * 32 + lane;
            u32 ahi0[4], ahi1[4];
            ldm4(ahi0, ha_hi + (u32)((ks*16) * 2));
            ldm4(ahi1, ha_hi + (u32)((16*AROW + ks*16) * 2));
            #pragma unroll
            for (int na = 0; na < 8; na++) {
                u64 vh = bhi[bix + na*32], vl = blo[bix + na*32];
                u32 bh0 = (u32)vh, bh1 = (u32)(vh >> 32);
                u32 bl0 = (u32)vl, bl1 = (u32)(vl >> 32);
                mma16816(acc[0][na], ahi0, bh0, bh1);
                mma16816(acc[1][na], ahi1, bh0, bh1);
                mma16816(acc[0][na], ahi0, bl0, bl1);
                mma16816(acc[1][na], ahi1, bl0, bl1);
            }
            u32 alo0[4], alo1[4];
            ldm4(alo0, ha_hi + HA_PART + (u32)((ks*16) * 2));
            ldm4(alo1, ha_hi + HA_PART + (u32)((16*AROW + ks*16) * 2));
            #pragma unroll
            for (int na = 0; na < 8; na++) {
                u64 vh = bhi[bix + na*32];
                u32 bh0 = (u32)vh, bh1 = (u32)(vh >> 32);
                mma16816(acc[0][na], alo0, bh0, bh1);
                mma16816(acc[1][na], alo1, bh0, bh1);
            }
        }

        #pragma unroll
        for (int ma = 0; ma < 2; ma++)
            #pragma unroll
            for (int hh = 0; hh < 2; hh++) {
                unsigned short hb[4], lb[4];
                #pragma unroll
                for (int m = 0; m < 4; m++) {
                    float gi = acc[ma][2*m  ][hh*2 + 0];
                    float gf = acc[ma][2*m  ][hh*2 + 1];
                    float gg = acc[ma][2*m+1][hh*2 + 0];
                    float go = acc[ma][2*m+1][hh*2 + 1];
                    float cn = sigm(gf) * c[ma][hh][m] + sigm(gi) * tanh_hw(gg);
                    c[ma][hh][m] = cn;
                    split_bf16(sigm(go) * tanh_hw(cn), hb[m], lb[m]);
                }
                int row  = rowbase + ma*16 + quad + hh*8;
                int colb = (wn*16 + tq*4) * 2;
                char* ph = sm + OFF_HA + wbuf*HA_BUF + row*AROW*2 + colb;
                uint2 vhi, vlo;
                vhi.x = (u32)hb[0] | ((u32)hb[1] << 16);
                vhi.y = (u32)hb[2] | ((u32)hb[3] << 16);
                vlo.x = (u32)lb[0] | ((u32)lb[1] << 16);
                vlo.y = (u32)lb[2] | ((u32)lb[3] << 16);
                *(uint2*)ph             = vhi;
                *(uint2*)(ph + HA_PART) = vlo;
            }
        HBAR(grp);
    }

    // final output (h_29 lives in buf[TOT_T & 1] = buf0)
    emit_out(sm, tid, TOT_T & 1, b0, Btot, out, DEC_T - 1);
}

extern "C" void kernel_launch(void* const* d_in, const int* in_sizes, int n_in,
                              void* d_out, int out_size) {
    const float* traj  = (const float*)d_in[0];
    const float* Wih_e = (const float*)d_in[1];
    const float* Whh_e = (const float*)d_in[2];
    const float* bih_e = (const float*)d_in[3];
    const float* bhh_e = (const float*)d_in[4];
    const float* Wih_d = (const float*)d_in[5];
    const float* Whh_d = (const float*)d_in[6];
    const float* bih_d = (const float*)d_in[7];
    const float* bhh_d = (const float*)d_in[8];
    const float* Wpos  = (const float*)d_in[9];
    const float* bpos  = (const float*)d_in[10];
    float* out = (float*)d_out;

    int B = in_sizes[0] / (2 * ENC_T);
    int grid = (B + TB - 1) / TB;

    cudaFuncSetAttribute(lstm_mma,
                         cudaFuncAttributeMaxDynamicSharedMemorySize, SMEM_SZ);

    lstm_mma<<<grid, NTH, SMEM_SZ>>>(traj, Wih_e, Whh_e, bih_e, bhh_e,
                                     Wih_d, Whh_d, bih_d, bhh_d,
                                     Wpos, bpos, out, B);
}

// round 16
// speedup vs baseline: 3.0174x; 1.1254x over previous
#include <cuda_runtime.h>
#include <cuda_bf16.h>

#define HID    64
#define ENC_T  20
#define DEC_T  30
#define TB     128
#define NTH    512
#define AROW   88           // bf16 cols per row of A/h buffer (bank-safe stride)
#define XROW   41           // x row stride in f32 (conflict-free)
#define TOT_T  (ENC_T + DEC_T)

typedef unsigned int u32;
typedef unsigned long long u64;

// ---- smem byte offsets ----
#define OFF_BHI   0                       // B frags hi: 4096 u64 = 32768 B
#define OFF_BLO   32768                   // 32768 B
#define OFF_HA    65536                   // h/A: 2 bufs x 2 parts x 128 x 88 bf16
#define HA_BUF    45056
#define HA_PART   22528
#define OFF_X     (OFF_HA + 2*HA_BUF)     // x: 128 x 41 f32 = 20992 B
#define OFF_WPOS  (OFF_X + 128*XROW*4)    // 128 f32
#define OFF_BPOS  (OFF_WPOS + 512)        // 2 f32 (+pad)
#define OFF_BTAB  (OFF_BPOS + 16)         // bias table: 256 f32
#define OFF_XW0   (OFF_BTAB + 1024)       // 256 f32
#define OFF_XW1   (OFF_XW0 + 1024)        // 256 f32
#define SMEM_SZ   (OFF_XW1 + 1024)

// per-quarter named barrier (ids 1..4, 128 threads each)
#define QBAR(grp) asm volatile("bar.sync %0, %1;" :: "r"((grp) + 1), "r"(128) : "memory")

// ---- activations ----
__device__ __forceinline__ float tanh_hw(float x) {
    float y; asm("tanh.approx.f32 %0, %1;" : "=f"(y) : "f"(x)); return y;
}
__device__ __forceinline__ float sigm(float x) {
    return fmaf(0.5f, tanh_hw(0.5f * x), 0.5f);
}

// ---- mma / ldmatrix wrappers ----
__device__ __forceinline__ void mma16816(float* d, const u32* a, u32 b0, u32 b1) {
    asm("mma.sync.aligned.m16n8k16.row.col.f32.bf16.bf16.f32 "
        "{%0,%1,%2,%3}, {%4,%5,%6,%7}, {%8,%9}, {%0,%1,%2,%3};"
        : "+f"(d[0]), "+f"(d[1]), "+f"(d[2]), "+f"(d[3])
        : "r"(a[0]), "r"(a[1]), "r"(a[2]), "r"(a[3]), "r"(b0), "r"(b1));
}
__device__ __forceinline__ void ldm4(u32* r, u32 addr) {
    asm volatile("ldmatrix.sync.aligned.m8n8.x4.shared.b16 {%0,%1,%2,%3}, [%4];"
        : "=r"(r[0]), "=r"(r[1]), "=r"(r[2]), "=r"(r[3]) : "r"(addr));
}

__device__ __forceinline__ void split2(float v, unsigned short& hb, unsigned short& lb) {
    __nv_bfloat16 hi = __float2bfloat16_rn(v);
    __nv_bfloat16 lo = __float2bfloat16_rn(v - __bfloat162float(hi));
    hb = __bfloat16_as_ushort(hi);
    lb = __bfloat16_as_ushort(lo);
}

// Build B fragments (exact mma layout), 4 k-steps, K=64 weights only.
// phase 0 = encoder W_hh; phase 1 = decoder W_ih + W_hh fused.
__device__ void build_bfrag(char* sm, int tid, int phase,
        const float* __restrict__ W, const float* __restrict__ W2)
{
    u64* bhi = (u64*)(sm + OFF_BHI);
    u64* blo = (u64*)(sm + OFF_BLO);
    for (int idx = tid; idx < 4096; idx += NTH) {
        int ks = idx >> 10, wn = (idx >> 8) & 3, na = (idx >> 5) & 7, T = idx & 31;
        int cc = T >> 2, tq = T & 3;
        int unit = wn * 16 + ((cc >> 1) << 2) + (na >> 1);
        int gate = ((na & 1) << 1) | (cc & 1);
        int grow = gate * 64 + unit;
        u32 phi[2] = {0, 0}, plo[2] = {0, 0};
        #pragma unroll
        for (int i = 0; i < 2; i++)
            #pragma unroll
            for (int e = 0; e < 2; e++) {
                int k = ks * 16 + tq * 2 + e + 8 * i;
                float v = phase ? (W[grow*64+k] + W2[grow*64+k]) : W[grow*64+k];
                unsigned short hb, lb;
                split2(v, hb, lb);
                phi[i] |= (u32)hb << (16 * e);
                plo[i] |= (u32)lb << (16 * e);
            }
        bhi[idx] = (u64)phi[0] | ((u64)phi[1] << 32);
        blo[idx] = (u64)plo[0] | ((u64)plo[1] << 32);
    }
}

// decoder output: quarter-local; pair (t,t^1) splits one 64-dot, shfl-combined
__device__ __forceinline__ void emit_out(char* sm, int tid, int buf, int b0, int Btot,
                                         float* __restrict__ out, int tstep) {
    const int grp = tid >> 7;
    const int loc = tid & 127;
    const int hd  = loc & 1, p = loc >> 1;
    const int row = grp * 32 + (p >> 1), j = p & 1;
    const __nv_bfloat162* ph = (const __nv_bfloat162*)(sm + OFF_HA + buf*HA_BUF + row*AROW*2);
    const __nv_bfloat162* pl = (const __nv_bfloat162*)((const char*)ph + HA_PART);
    const float2* wp2 = (const float2*)((const float*)(sm + OFF_WPOS) + j*64);
    float a = 0.f;
    #pragma unroll
    for (int i = 0; i < 16; i++) {
        int u2 = hd * 16 + i;
        __nv_bfloat162 hv = ph[u2], lv = pl[u2];
        float2 w = wp2[u2];
        a += (__bfloat162float(hv.x) + __bfloat162float(lv.x)) * w.x
           + (__bfloat162float(hv.y) + __bfloat162float(lv.y)) * w.y;
    }
    a += __shfl_xor_sync(0xFFFFFFFFu, a, 1);
    if (hd == 0 && b0 + row < Btot)
        out[(size_t)(b0 + row) * (2*DEC_T) + tstep*2 + j]
            = a + ((const float*)(sm + OFF_BPOS))[j];
}

__global__ void __launch_bounds__(NTH, 1)
lstm_mma(const float* __restrict__ traj,
         const float* __restrict__ Wih_e, const float* __restrict__ Whh_e,
         const float* __restrict__ bih_e, const float* __restrict__ bhh_e,
         const float* __restrict__ Wih_d, const float* __restrict__ Whh_d,
         const float* __restrict__ bih_d, const float* __restrict__ bhh_d,
         const float* __restrict__ Wpos,  const float* __restrict__ bpos,
         float* __restrict__ out, int Btot)
{
    extern __shared__ char sm[];
    const int tid  = threadIdx.x;
    const int lane = tid & 31, warp = tid >> 5;
    const int grp  = warp >> 2;                 // quarter: rows grp*32 .. grp*32+31
    const int wn   = warp & 3;                  // n-band (units wn*16)
    const int rowbase = grp * 32;
    const int quad = lane >> 2, tq = lane & 3;
    const int b0   = blockIdx.x * TB;

    // ---------------- setup (global) ----------------
    build_bfrag(sm, tid, 0, Whh_e, (const float*)0);

    // tables: bias (encoder) + x-weight columns, col-id mapping i -> grow
    {
        float* btab = (float*)(sm + OFF_BTAB);
        float* xw0  = (float*)(sm + OFF_XW0);
        float* xw1  = (float*)(sm + OFF_XW1);
        for (int i = tid; i < 256; i += NTH) {
            int wn_ = i >> 6, tq_ = (i >> 4) & 3, na_ = (i >> 1) & 7, par = i & 1;
            int unit = wn_*16 + tq_*4 + (na_ >> 1);
            int gate = ((na_ & 1) << 1) | par;
            int grow = gate * 64 + unit;
            btab[i] = bih_e[grow] + bhh_e[grow];
            xw0[i]  = Wih_e[grow*2 + 0];
            xw1[i]  = Wih_e[grow*2 + 1];
        }
    }
    {   // x staging: xs[row*XROW + t*2 + sel]
        float* xs = (float*)(sm + OFF_X);
        for (int i = tid; i < TB * 2 * ENC_T; i += NTH) {
            int row = i / 40, r = i % 40;
            xs[row*XROW + r] = (b0 + row < Btot) ? traj[(size_t)b0 * 40 + i] : 0.f;
        }
    }
    // zero h cols 0-63 of buf0 (both parts)
    for (int i = tid; i < 2 * 128 * 64; i += NTH) {
        int col = i & 63, row = (i >> 6) & 127, part = i >> 13;
        *(unsigned short*)(sm + OFF_HA + part*HA_PART + (row*AROW + col)*2) = 0;
    }
    if (tid < 128) ((float*)(sm + OFF_WPOS))[tid] = Wpos[tid];
    if (tid < 2)   ((float*)(sm + OFF_BPOS))[tid] = bpos[tid];

    float c[2][2][4];
    #pragma unroll
    for (int a = 0; a < 2; a++)
        #pragma unroll
        for (int h = 0; h < 2; h++)
            #pragma unroll
            for (int m = 0; m < 4; m++) c[a][h][m] = 0.f;

    const u32 smbase = (u32)__cvta_generic_to_shared(sm);
    const int lrow = (lane & 7) + ((lane >> 3) & 1) * 8;
    const u32 ldm0 = (u32)(((rowbase + lrow) * AROW + (lane >> 4) * 8) * 2);

    __syncthreads();

    // ================ encoder: 20 steps (K=64 + fp32 x/bias init) ================
    for (int s = 0; s < ENC_T; s++) {
        const int rbuf = s & 1, wbuf = rbuf ^ 1;

        float acc[2][8][4];
        {   // acc init: bias + x_s @ Wx  (fp32, exact)
            const float4* bt4 = (const float4*)((const float*)(sm + OFF_BTAB) + ((wn*4 + tq) << 4));
            const float4* w04 = (const float4*)((const float*)(sm + OFF_XW0)  + ((wn*4 + tq) << 4));
            const float4* w14 = (const float4*)((const float*)(sm + OFF_XW1)  + ((wn*4 + tq) << 4));
            float bvv[16], w0v[16], w1v[16];
            #pragma unroll
            for (int q4 = 0; q4 < 4; q4++) {
                *(float4*)(bvv + 4*q4) = bt4[q4];
                *(float4*)(w0v + 4*q4) = w04[q4];
                *(float4*)(w1v + 4*q4) = w14[q4];
            }
            const float* xs = (const float*)(sm + OFF_X);
            float xv0[2][2], xv1[2][2];
            #pragma unroll
            for (int ma = 0; ma < 2; ma++)
                #pragma unroll
                for (int hh = 0; hh < 2; hh++) {
                    int row = rowbase + ma*16 + quad + hh*8;
                    xv0[ma][hh] = xs[row*XROW + 2*s];
                    xv1[ma][hh] = xs[row*XROW + 2*s + 1];
                }
            #pragma unroll
            for (int ma = 0; ma < 2; ma++)
                #pragma unroll
                for (int na = 0; na < 8; na++)
                    #pragma unroll
                    for (int hh = 0; hh < 2; hh++)
                        #pragma unroll
                        for (int par = 0; par < 2; par++) {
                            int cix = na*2 + par;
                            acc[ma][na][hh*2+par] =
                                fmaf(xv1[ma][hh], w1v[cix],
                                fmaf(xv0[ma][hh], w0v[cix], bvv[cix]));
                        }
        }

        const u32 ha_hi = smbase + OFF_HA + (u32)rbuf * HA_BUF + ldm0;
        const u64* __restrict__ bhi = (const u64*)(sm + OFF_BHI);
        const u64* __restrict__ blo = (const u64*)(sm + OFF_BLO);

        #pragma unroll
        for (int ks = 0; ks < 4; ks++) {
            const int bix = ((ks * 4 + wn) * 8) * 32 + lane;
            u32 ahi0[4], ahi1[4], alo0[4], alo1[4];
            ldm4(ahi0, ha_hi + (u32)((ks*16) * 2));
            ldm4(ahi1, ha_hi + (u32)((16*AROW + ks*16) * 2));
            ldm4(alo0, ha_hi + HA_PART + (u32)((ks*16) * 2));
            ldm4(alo1, ha_hi + HA_PART + (u32)((16*AROW + ks*16) * 2));
            #pragma unroll
            for (int na = 0; na < 8; na++) {
                u64 vh = bhi[bix + na*32], vl = blo[bix + na*32];
                u32 bh0 = (u32)vh, bh1 = (u32)(vh >> 32);
                u32 bl0 = (u32)vl, bl1 = (u32)(vl >> 32);
                mma16816(acc[0][na], ahi0, bh0, bh1);
                mma16816(acc[1][na], ahi1, bh0, bh1);
                mma16816(acc[0][na], ahi0, bl0, bl1);
                mma16816(acc[1][na], ahi1, bl0, bl1);
                mma16816(acc[0][na], alo0, bh0, bh1);
                mma16816(acc[1][na], alo1, bh0, bh1);
            }
        }

        #pragma unroll
        for (int ma = 0; ma < 2; ma++)
            #pragma unroll
            for (int hh = 0; hh < 2; hh++) {
                unsigned short hb[4], lb[4];
                #pragma unroll
                for (int m = 0; m < 4; m++) {
                    float gi = acc[ma][2*m  ][hh*2 + 0];
                    float gf = acc[ma][2*m  ][hh*2 + 1];
                    float gg = acc[ma][2*m+1][hh*2 + 0];
                    float go = acc[ma][2*m+1][hh*2 + 1];
                    float cn = sigm(gf) * c[ma][hh][m] + sigm(gi) * tanh_hw(gg);
                    c[ma][hh][m] = cn;
                    split2(sigm(go) * tanh_hw(cn), hb[m], lb[m]);
                }
                int row  = rowbase + ma*16 + quad + hh*8;
                int colb = (wn*16 + tq*4) * 2;
                char* ph = sm + OFF_HA + wbuf*HA_BUF + row*AROW*2 + colb;
                uint2 vhi, vlo;
                vhi.x = (u32)hb[0] | ((u32)hb[1] << 16);
                vhi.y = (u32)hb[2] | ((u32)hb[3] << 16);
                vlo.x = (u32)lb[0] | ((u32)lb[1] << 16);
                vlo.y = (u32)lb[2] | ((u32)lb[3] << 16);
                *(uint2*)ph             = vhi;
                *(uint2*)(ph + HA_PART) = vlo;
            }
        QBAR(grp);
    }

    // ---- decoder transition (global): rebuild B fused + decoder bias table ----
    __syncthreads();
    build_bfrag(sm, tid, 1, Wih_d, Whh_d);
    {
        float* btab = (float*)(sm + OFF_BTAB);
        for (int i = tid; i < 256; i += NTH) {
            int wn_ = i >> 6, tq_ = (i >> 4) & 3, na_ = (i >> 1) & 7, par = i & 1;
            int unit = wn_*16 + tq_*4 + (na_ >> 1);
            int gate = ((na_ & 1) << 1) | par;
            int grow = gate * 64 + unit;
            btab[i] = bih_d[grow] + bhh_d[grow];
        }
    }
    __syncthreads();

    // ================ decoder: 30 steps (K=64, bias in acc) ================
    for (int d = 0; d < DEC_T; d++) {
        const int s = ENC_T + d;
        const int rbuf = s & 1, wbuf = rbuf ^ 1;

        if (d >= 1) emit_out(sm, tid, rbuf, b0, Btot, out, d - 1);

        float acc[2][8][4];
        {
            const float4* bt4 = (const float4*)((const float*)(sm + OFF_BTAB) + ((wn*4 + tq) << 4));
            float bvv[16];
            #pragma unroll
            for (int q4 = 0; q4 < 4; q4++) *(float4*)(bvv + 4*q4) = bt4[q4];
            #pragma unroll
            for (int na = 0; na < 8; na++) {
                float b0v = bvv[na*2], b1v = bvv[na*2+1];
                acc[0][na][0] = b0v; acc[0][na][1] = b1v;
                acc[0][na][2] = b0v; acc[0][na][3] = b1v;
                acc[1][na][0] = b0v; acc[1][na][1] = b1v;
                acc[1][na][2] = b0v; acc[1][na][3] = b1v;
            }
        }

        const u32 ha_hi = smbase + OFF_HA + (u32)rbuf * HA_BUF + ldm0;
        const u64* __restrict__ bhi = (const u64*)(sm + OFF_BHI);
        const u64* __restrict__ blo = (const u64*)(sm + OFF_BLO);

        #pragma unroll
        for (int ks = 0; ks < 4; ks++) {
            const int bix = ((ks * 4 + wn) * 8) * 32 + lane;
            u32 ahi0[4], ahi1[4], alo0[4], alo1[4];
            ldm4(ahi0, ha_hi + (u32)((ks*16) * 2));
            ldm4(ahi1, ha_hi + (u32)((16*AROW + ks*16) * 2));
            ldm4(alo0, ha_hi + HA_PART + (u32)((ks*16) * 2));
            ldm4(alo1, ha_hi + HA_PART + (u32)((16*AROW + ks*16) * 2));
            #pragma unroll
            for (int na = 0; na < 8; na++) {
                u64 vh = bhi[bix + na*32], vl = blo[bix + na*32];
                u32 bh0 = (u32)vh, bh1 = (u32)(vh >> 32);
                u32 bl0 = (u32)vl, bl1 = (u32)(vl >> 32);
                mma16816(acc[0][na], ahi0, bh0, bh1);
                mma16816(acc[1][na], ahi1, bh0, bh1);
                mma16816(acc[0][na], ahi0, bl0, bl1);
                mma16816(acc[1][na], ahi1, bl0, bl1);
                mma16816(acc[0][na], alo0, bh0, bh1);
                mma16816(acc[1][na], alo1, bh0, bh1);
            }
        }

        #pragma unroll
        for (int ma = 0; ma < 2; ma++)
            #pragma unroll
            for (int hh = 0; hh < 2; hh++) {
                unsigned short hb[4], lb[4];
                #pragma unroll
                for (int m = 0; m < 4; m++) {
                    float gi = acc[ma][2*m  ][hh*2 + 0];
                    float gf = acc[ma][2*m  ][hh*2 + 1];
                    float gg = acc[ma][2*m+1][hh*2 + 0];
                    float go = acc[ma][2*m+1][hh*2 + 1];
                    float cn = sigm(gf) * c[ma][hh][m] + sigm(gi) * tanh_hw(gg);
                    c[ma][hh][m] = cn;
                    split2(sigm(go) * tanh_hw(cn), hb[m], lb[m]);
                }
                int row  = rowbase + ma*16 + quad + hh*8;
                int colb = (wn*16 + tq*4) * 2;
                char* ph = sm + OFF_HA + wbuf*HA_BUF + row*AROW*2 + colb;
                uint2 vhi, vlo;
                vhi.x = (u32)hb[0] | ((u32)hb[1] << 16);
                vhi.y = (u32)hb[2] | ((u32)hb[3] << 16);
                vlo.x = (u32)lb[0] | ((u32)lb[1] << 16);
                vlo.y = (u32)lb[2] | ((u32)lb[3] << 16);
                *(uint2*)ph             = vhi;
                *(uint2*)(ph + HA_PART) = vlo;
            }
        QBAR(grp);
    }

    // final output (h_29 lives in buf[TOT_T & 1] = buf0)
    emit_out(sm, tid, TOT_T & 1, b0, Btot, out, DEC_T - 1);
}

extern "C" void kernel_launch(void* const* d_in, const int* in_sizes, int n_in,
                              void* d_out, int out_size) {
    const float* traj  = (const float*)d_in[0];
    const float* Wih_e = (const float*)d_in[1];
    const float* Whh_e = (const float*)d_in[2];
    const float* bih_e = (const float*)d_in[3];
    const float* bhh_e = (const float*)d_in[4];
    const float* Wih_d = (const float*)d_in[5];
    const float* Whh_d = (const float*)d_in[6];
    const float* bih_d = (const float*)d_in[7];
    const float* bhh_d = (const float*)d_in[8];
    const float* Wpos  = (const float*)d_in[9];
    const float* bpos  = (const float*)d_in[10];
    float* out = (float*)d_out;

    int B = in_sizes[0] / (2 * ENC_T);
    int grid = (B + TB - 1) / TB;

    cudaFuncSetAttribute(lstm_mma,
                         cudaFuncAttributeMaxDynamicSharedMemorySize, SMEM_SZ);

    lstm_mma<<<grid, NTH, SMEM_SZ>>>(traj, Wih_e, Whh_e, bih_e, bhh_e,
                                     Wih_d, Whh_d, bih_d, bhh_d,
                                     Wpos, bpos, out, B);
}